// round 1
// baseline (speedup 1.0000x reference)
#include <cuda_runtime.h>
#include <math.h>

// ---------------- problem constants ----------------
#define Bq 16
#define Cq 256
#define Hq 64
#define Wq 64
#define Nq 4096            // Hq*Wq
#define NHq 8
#define CRq 128
#define HIDq 1024
#define HALFq 512
#define Mrows (Bq*Nq)      // 65536

// ---------------- scratch layout (floats) ----------------
#define OFF_MH   0ull
#define OFF_MW   262144ull
#define OFF_GH   524288ull
#define OFF_GW   786432ull
#define OFF_RES1 1048576ull
#define OFF_LN1  17825792ull
#define OFF_Q    34603008ull
#define OFF_R1   42991616ull
#define OFF_R2   44040192ull
#define OFF_D    44105728ull
#define OFF_XA   44171264ull
#define OFF_K    44204032ull
#define OFF_VT   44236800ull
#define OFF_V2   44302336ull
#define OFF_AO   44367872ull
#define OFF_T2   61145088ull
#define OFF_LN2  77922304ull
#define OFF_HH   94699520ull
#define OFF_X2   161808384ull
#define OFF_GT   195362816ull
#define OFF_TF   228917248ull
#define G_TOTAL  245694464ull

static __device__ float g_s[G_TOTAL];

#define DINL __device__ __forceinline__

DINL float gelu_f(float x) { return 0.5f * x * (1.0f + erff(x * 0.70710678118654752f)); }

// block reduce of (sum, sumsq); sh must hold >= 64 floats
DINL void blockReduce2(float& s, float& q, float* sh) {
    int lane = threadIdx.x & 31, wid = threadIdx.x >> 5;
#pragma unroll
    for (int o = 16; o > 0; o >>= 1) {
        s += __shfl_down_sync(0xffffffffu, s, o);
        q += __shfl_down_sync(0xffffffffu, q, o);
    }
    if (lane == 0) { sh[wid] = s; sh[32 + wid] = q; }
    __syncthreads();
    if (threadIdx.x == 0) {
        float ss = 0.f, qq = 0.f;
        int nw = blockDim.x >> 5;
        for (int i = 0; i < nw; i++) { ss += sh[i]; qq += sh[32 + i]; }
        sh[0] = ss; sh[32] = qq;
    }
    __syncthreads();
    s = sh[0]; q = sh[32];
}

// ---------------- K1: coordinate pooled means ----------------
// grid = B*C blocks, 64 threads
__global__ void k_mean(const float* __restrict__ x, float* __restrict__ mh, float* __restrict__ mw) {
    int bc = blockIdx.x;
    const float* p = x + (size_t)bc * 4096;
    int w = threadIdx.x;
    __shared__ float part[128];
    float colsum = 0.f;
    for (int r = 0; r < 64; r++) {
        float v = p[r * 64 + w];
        colsum += v;
        float s = v;
#pragma unroll
        for (int o = 16; o > 0; o >>= 1) s += __shfl_down_sync(0xffffffffu, s, o);
        if ((w & 31) == 0) part[(w >> 5) * 64 + r] = s;
    }
    __syncthreads();
    mh[(size_t)bc * 64 + w] = (part[w] + part[64 + w]) * (1.f / 64.f);  // mean over W -> [B,C,H]
    mw[(size_t)bc * 64 + w] = colsum * (1.f / 64.f);                    // mean over H -> [B,C,W]
}

// ---------------- K2: dwconv1d(k=7) + GroupNorm(16) + ReLU ----------------
// grid = (16 groups, B, 2), 256 threads
__global__ void k_sdagn(const float* __restrict__ mh, const float* __restrict__ mw,
                        const float* __restrict__ w7, const float* __restrict__ gnw,
                        const float* __restrict__ gnb, float* __restrict__ gh, float* __restrict__ gw_) {
    int grp = blockIdx.x, b = blockIdx.y;
    const float* mean = (blockIdx.z ? mw : mh) + (size_t)b * Cq * 64;
    float* out = (blockIdx.z ? gw_ : gh) + (size_t)b * Cq * 64;
    __shared__ float buf[1024];
    __shared__ float sh[64];
    int tid = threadIdx.x;
    float ls = 0.f, lq = 0.f;
#pragma unroll
    for (int j = 0; j < 4; j++) {
        int idx = tid + j * 256;
        int c = grp * 16 + (idx >> 6), l = idx & 63;
        const float* m = mean + c * 64;
        float acc = 0.f;
#pragma unroll
        for (int k = 0; k < 7; k++) {
            int ll = l + k - 3;
            if (ll >= 0 && ll < 64) acc += m[ll] * w7[c * 7 + k];
        }
        buf[idx] = acc; ls += acc; lq += acc * acc;
    }
    blockReduce2(ls, lq, sh);
    float mu = ls * (1.f / 1024.f);
    float rstd = rsqrtf(lq * (1.f / 1024.f) - mu * mu + 1e-5f);
#pragma unroll
    for (int j = 0; j < 4; j++) {
        int idx = tid + j * 256;
        int c = grp * 16 + (idx >> 6), l = idx & 63;
        float y = (buf[idx] - mu) * rstd * gnw[c] + gnb[c];
        out[(size_t)c * 64 + l] = fmaxf(y, 0.f);
    }
}

// ---------------- K3: modulate + to tokens + LN1 ----------------
// grid = (128 n-chunks, B), block (32,8)
__global__ void k_tokens(const float* __restrict__ x, const float* __restrict__ gh,
                         const float* __restrict__ gw_, const float* __restrict__ n1w,
                         const float* __restrict__ n1b, float* __restrict__ res, float* __restrict__ ln) {
    int b = blockIdx.y;
    int n0 = blockIdx.x * 32;
    int h = n0 >> 6, w0 = n0 & 63;
    int nx = threadIdx.x, cy = threadIdx.y;
    __shared__ float tile[256][33];
    __shared__ float mu[32], rs[32];
    const float* ghb = gh + (size_t)b * Cq * 64;
    const float* gwb = gw_ + (size_t)b * Cq * 64;
    const float* xb = x + (size_t)b * Cq * Nq;
#pragma unroll 4
    for (int j = 0; j < 32; j++) {
        int c = cy * 32 + j;
        float v = xb[(size_t)c * Nq + h * 64 + w0 + nx] * ghb[c * 64 + h] * gwb[c * 64 + w0 + nx];
        tile[c][nx] = v;
    }
    __syncthreads();
    int tid = cy * 32 + nx, lane = tid & 31, warp = tid >> 5;
    for (int nn = warp; nn < 32; nn += 8) {
        float s = 0.f, q = 0.f;
        for (int c = lane; c < 256; c += 32) { float v = tile[c][nn]; s += v; q += v * v; }
#pragma unroll
        for (int o = 16; o > 0; o >>= 1) {
            s += __shfl_down_sync(0xffffffffu, s, o);
            q += __shfl_down_sync(0xffffffffu, q, o);
        }
        if (lane == 0) {
            float m = s * (1.f / 256.f);
            mu[nn] = m; rs[nn] = rsqrtf(q * (1.f / 256.f) - m * m + 1e-6f);
        }
    }
    __syncthreads();
    float* resp = res + ((size_t)b * Nq + n0) * Cq;
    float* lnp = ln + ((size_t)b * Nq + n0) * Cq;
    for (int idx = tid; idx < 32 * 256; idx += 256) {
        int nl = idx >> 8, c = idx & 255;
        float v = tile[c][nl];
        resp[(size_t)nl * 256 + c] = v;
        lnp[(size_t)nl * 256 + c] = (v - mu[nl]) * rs[nl] * n1w[c] + n1b[c];
    }
}

// ---------------- reduction path (tiny) ----------------
// dw conv k4 s4 p0: 64x64 -> 16x16   grid(256,B) block 256
__global__ void k_red1(const float* __restrict__ ln1, const float* __restrict__ rw,
                       const float* __restrict__ rb, float* __restrict__ r1) {
    int p = blockIdx.x, b = blockIdx.y, c = threadIdx.x;
    int i = p >> 4, j = p & 15;
    float acc = rb[c];
    const float* base = ln1 + (size_t)b * Nq * Cq + c;
#pragma unroll
    for (int a = 0; a < 4; a++)
#pragma unroll
        for (int d = 0; d < 4; d++) {
            int n = (4 * i + a) * 64 + 4 * j + d;
            acc += base[(size_t)n * 256] * rw[c * 16 + a * 4 + d];
        }
    r1[((size_t)b * 256 + p) * 256 + c] = acc;
}

// 16x16 -> 4x4   grid(16,B) block 256
__global__ void k_red2(const float* __restrict__ r1, const float* __restrict__ rw,
                       const float* __restrict__ rb, float* __restrict__ r2) {
    int p2 = blockIdx.x, b = blockIdx.y, c = threadIdx.x;
    int i2 = p2 >> 2, j2 = p2 & 3;
    float acc = rb[c];
#pragma unroll
    for (int a = 0; a < 4; a++)
#pragma unroll
        for (int d = 0; d < 4; d++) {
            int p = (4 * i2 + a) * 16 + (4 * j2 + d);
            acc += r1[((size_t)b * 256 + p) * 256 + c] * rw[c * 16 + a * 4 + d];
        }
    r2[((size_t)b * 16 + p2) * 256 + c] = acc;
}

// depthwise 3x3 pad1 on 4x4   grid(16,B) block 256
__global__ void k_dw3(const float* __restrict__ r2, const float* __restrict__ dww,
                      const float* __restrict__ dwb, float* __restrict__ dd) {
    int p = blockIdx.x, b = blockIdx.y, c = threadIdx.x;
    int i = p >> 2, j = p & 3;
    float acc = dwb[c];
#pragma unroll
    for (int a = 0; a < 3; a++) {
        int ii = i + a - 1;
        if (ii < 0 || ii >= 4) continue;
#pragma unroll
        for (int d = 0; d < 3; d++) {
            int jj = j + d - 1;
            if (jj < 0 || jj >= 4) continue;
            acc += r2[((size_t)b * 16 + ii * 4 + jj) * 256 + c] * dww[c * 9 + a * 3 + d];
        }
    }
    dd[((size_t)b * 16 + p) * 256 + c] = acc;
}

// 1x1 conv 256->128 + LN(128, eps 1e-5) + gelu   grid(16,B) block 128
__global__ void k_na(const float* __restrict__ dd, const float* __restrict__ cw,
                     const float* __restrict__ cb, const float* __restrict__ naw,
                     const float* __restrict__ nab, float* __restrict__ xa) {
    int p = blockIdx.x, b = blockIdx.y, o = threadIdx.x;
    __shared__ float ds[256];
    __shared__ float sh[64];
    const float* dp = dd + ((size_t)b * 16 + p) * 256;
    ds[o] = dp[o]; ds[o + 128] = dp[o + 128];
    __syncthreads();
    float e = cb[o];
    for (int c = 0; c < 256; c++) e += ds[c] * cw[o * 256 + c];
    float s = e, q = e * e;
    blockReduce2(s, q, sh);
    float mu = s * (1.f / 128.f);
    float rstd = rsqrtf(q * (1.f / 128.f) - mu * mu + 1e-5f);
    float y = (e - mu) * rstd * naw[o] + nab[o];
    xa[((size_t)b * 16 + p) * 128 + o] = gelu_f(y);
}

// k,v projections of the 16-token reduced sequence  grid(16,B) block 256
__global__ void k_kv(const float* __restrict__ xa, const float* __restrict__ kw,
                     const float* __restrict__ vw, float* __restrict__ kk, float* __restrict__ vt) {
    int p = blockIdx.x, b = blockIdx.y, t = threadIdx.x;
    __shared__ float xs[128];
    if (t < 128) xs[t] = xa[((size_t)b * 16 + p) * 128 + t];
    __syncthreads();
    if (t < 128) {
        float a = 0.f;
        for (int c = 0; c < 128; c++) a += xs[c] * kw[c * 128 + t];
        kk[((size_t)b * 16 + p) * 128 + t] = a;
    }
    float a2 = 0.f;
    for (int c = 0; c < 128; c++) a2 += xs[c] * vw[c * 256 + t];
    vt[((size_t)b * 16 + p) * 256 + t] = a2;
}

// CPE: depthwise 3x3 on v viewed as [B,256,4,4], added to v   grid(16,B) block 256
__global__ void k_cpe(const float* __restrict__ vt, const float* __restrict__ cw,
                      const float* __restrict__ cb, float* __restrict__ v2) {
    int p = blockIdx.x, b = blockIdx.y, ch = threadIdx.x;
    int i = p >> 2, j = p & 3;
    float acc = cb[ch];
#pragma unroll
    for (int a = 0; a < 3; a++) {
        int ii = i + a - 1;
        if (ii < 0 || ii >= 4) continue;
#pragma unroll
        for (int d = 0; d < 3; d++) {
            int jj = j + d - 1;
            if (jj < 0 || jj >= 4) continue;
            acc += vt[((size_t)b * 16 + ii * 4 + jj) * 256 + ch] * cw[ch * 9 + a * 3 + d];
        }
    }
    v2[((size_t)b * 16 + p) * 256 + ch] = vt[((size_t)b * 16 + p) * 256 + ch] + acc;
}

// ---------------- fused attention: softmax(q k^T * 0.25) v ----------------
// grid(128,B) block 256 : 32 tokens x 8 heads per block
__global__ void k_attn(const float* __restrict__ q, const float* __restrict__ kk,
                       const float* __restrict__ v2, float* __restrict__ ao) {
    __shared__ float ks[8 * 260];
    __shared__ float vs[8 * 516];
    int b = blockIdx.y;
    int tid = threadIdx.x;
    for (int idx = tid; idx < 2048; idx += 256) {
        int head = idx >> 8, r = idx & 255, m = r >> 4, i = r & 15;
        ks[head * 260 + m * 16 + i] = kk[((size_t)b * 16 + m) * 128 + head * 16 + i];
    }
    for (int idx = tid; idx < 4096; idx += 256) {
        int head = idx >> 9, r = idx & 511, m = r >> 5, d = r & 31;
        vs[head * 516 + m * 32 + d] = v2[((size_t)b * 16 + m) * 256 + head * 32 + d];
    }
    __syncthreads();
    int nl = tid >> 3, head = tid & 7;
    int n = blockIdx.x * 32 + nl;
    const float* qp = q + ((size_t)b * Nq + n) * 128 + head * 16;
    float qr[16];
#pragma unroll
    for (int i = 0; i < 16; i++) qr[i] = qp[i];
    const float* kh = ks + head * 260;
    float s[16];
    float mx = -1e30f;
#pragma unroll
    for (int m = 0; m < 16; m++) {
        float a = 0.f;
#pragma unroll
        for (int i = 0; i < 16; i++) a += qr[i] * kh[m * 16 + i];
        a *= 0.25f;
        s[m] = a;
        mx = fmaxf(mx, a);
    }
    float sum = 0.f;
#pragma unroll
    for (int m = 0; m < 16; m++) { s[m] = __expf(s[m] - mx); sum += s[m]; }
    float inv = 1.f / sum;
    float o[32];
#pragma unroll
    for (int d = 0; d < 32; d++) o[d] = 0.f;
    const float* vh = vs + head * 516;
#pragma unroll
    for (int m = 0; m < 16; m++) {
        float pm = s[m] * inv;
#pragma unroll
        for (int d = 0; d < 32; d++) o[d] += pm * vh[m * 32 + d];
    }
    float* op = ao + ((size_t)b * Nq + n) * 256 + head * 32;
#pragma unroll
    for (int d = 0; d < 32; d++) op[d] = o[d];
}

// ---------------- generic SGEMM C = A[M,K] x Bw[K,N] (+bias +gelu +res) ----------------
// OP bits: 1=bias, 2=gelu, 4=residual add. 128x128 tile, BK=8, 256 threads, 8x8/thread.
template <int OP>
__global__ __launch_bounds__(256) void k_gemm(const float* __restrict__ A, const float* __restrict__ Bw,
                                              const float* __restrict__ bias, const float* __restrict__ res,
                                              float* __restrict__ C, int M, int N, int K) {
    __shared__ float As[8][128];
    __shared__ float Bs[8][128];
    int tid = threadIdx.x;
    int m0 = blockIdx.y * 128, n0 = blockIdx.x * 128;
    int tx = tid & 15, ty = tid >> 4;
    float acc[8][8];
#pragma unroll
    for (int i = 0; i < 8; i++)
#pragma unroll
        for (int j = 0; j < 8; j++) acc[i][j] = 0.f;

    int arow = tid >> 1;
    int acol = (tid & 1) * 4;
    int brow = tid >> 5;
    int bcol = (tid & 31) * 4;
    const float* Ap = A + (size_t)(m0 + arow) * K + acol;
    const float* Bp = Bw + (size_t)brow * N + n0 + bcol;

    for (int k0 = 0; k0 < K; k0 += 8) {
        float4 a = *(const float4*)(Ap + k0);
        float4 bb = *(const float4*)(Bp + (size_t)k0 * N);
        As[acol + 0][arow] = a.x;
        As[acol + 1][arow] = a.y;
        As[acol + 2][arow] = a.z;
        As[acol + 3][arow] = a.w;
        *(float4*)&Bs[brow][bcol] = bb;
        __syncthreads();
#pragma unroll
        for (int k = 0; k < 8; k++) {
            float ar[8], br[8];
#pragma unroll
            for (int i = 0; i < 8; i++) ar[i] = As[k][ty * 8 + i];
#pragma unroll
            for (int j = 0; j < 8; j++) br[j] = Bs[k][tx * 8 + j];
#pragma unroll
            for (int i = 0; i < 8; i++)
#pragma unroll
                for (int j = 0; j < 8; j++) acc[i][j] += ar[i] * br[j];
        }
        __syncthreads();
    }

#pragma unroll
    for (int i = 0; i < 8; i++) {
        int r = m0 + ty * 8 + i;
#pragma unroll
        for (int j = 0; j < 8; j++) {
            int c = n0 + tx * 8 + j;
            float v = acc[i][j];
            if (OP & 1) v += bias[c];
            if (OP & 2) v = gelu_f(v);
            if (OP & 4) v += res[(size_t)r * N + c];
            C[(size_t)r * N + c] = v;
        }
    }
}

// ---------------- generic LayerNorm over last dim (256 or 512) ----------------
// grid = rows, block 256
__global__ void k_ln(const float* __restrict__ in, int istr, const float* __restrict__ w,
                     const float* __restrict__ b, float* __restrict__ out, int ostr, int D, float eps) {
    size_t row = blockIdx.x;
    const float* ip = in + row * (size_t)istr;
    int cnt = D >> 8;
    float v[2];
    float s = 0.f, q = 0.f;
    for (int j = 0; j < cnt; j++) {
        float x = ip[threadIdx.x + j * 256];
        v[j] = x; s += x; q += x * x;
    }
    __shared__ float sh[64];
    blockReduce2(s, q, sh);
    float mu = s / (float)D;
    float rstd = rsqrtf(q / (float)D - mu * mu + eps);
    float* op = out + row * (size_t)ostr;
    for (int j = 0; j < cnt; j++) {
        int c = threadIdx.x + j * 256;
        op[c] = (v[j] - mu) * rstd * w[c] + b[c];
    }
}

// ---------------- depthwise 3x3 gate conv + multiply by x1 ----------------
// grid(4096,B) block 256, 2 channels per thread
__global__ void k_gconv(const float* __restrict__ x2, const float* __restrict__ hbuf,
                        const float* __restrict__ gcw, const float* __restrict__ gcb,
                        float* __restrict__ gated) {
    int n = blockIdx.x, b = blockIdx.y;
    int hh = n >> 6, ww = n & 63;
    const float* xb = x2 + (size_t)b * Nq * 512;
#pragma unroll
    for (int r = 0; r < 2; r++) {
        int ch = threadIdx.x + r * 256;
        float acc = gcb[ch];
#pragma unroll
        for (int a = 0; a < 3; a++) {
            int hi = hh + a - 1;
            if (hi < 0 || hi >= 64) continue;
#pragma unroll
            for (int d = 0; d < 3; d++) {
                int wi = ww + d - 1;
                if (wi < 0 || wi >= 64) continue;
                acc += xb[(size_t)(hi * 64 + wi) * 512 + ch] * gcw[ch * 9 + a * 3 + d];
            }
        }
        float x1 = hbuf[((size_t)b * Nq + n) * 1024 + ch];
        gated[((size_t)b * Nq + n) * 512 + ch] = x1 * acc;
    }
}

// ---------------- final [B,N,C] -> [B,C,H,W] transpose ----------------
// grid(128, 8, B) block(32,8)
__global__ void k_tr(const float* __restrict__ tf, float* __restrict__ out) {
    __shared__ float t[32][33];
    int n0 = blockIdx.x * 32, c0 = blockIdx.y * 32, b = blockIdx.z;
    const float* ip = tf + (size_t)b * Nq * Cq;
    float* op = out + (size_t)b * Cq * Nq;
#pragma unroll
    for (int j = 0; j < 4; j++) {
        int i = threadIdx.y + j * 8;
        t[i][threadIdx.x] = ip[(size_t)(n0 + i) * 256 + c0 + threadIdx.x];
    }
    __syncthreads();
#pragma unroll
    for (int j = 0; j < 4; j++) {
        int i = threadIdx.y + j * 8;
        op[(size_t)(c0 + i) * 4096 + n0 + threadIdx.x] = t[threadIdx.x][i];
    }
}

// ---------------- host launch ----------------
extern "C" void kernel_launch(void* const* d_in, const int* in_sizes, int n_in,
                              void* d_out, int out_size) {
    const float* x         = (const float*)d_in[0];
    const float* sda_conv_w= (const float*)d_in[1];
    const float* sda_gn_w  = (const float*)d_in[2];
    const float* sda_gn_b  = (const float*)d_in[3];
    const float* norm1_w   = (const float*)d_in[4];
    const float* norm1_b   = (const float*)d_in[5];
    const float* red_w     = (const float*)d_in[6];
    const float* red_b     = (const float*)d_in[7];
    const float* dw_w      = (const float*)d_in[8];
    const float* dw_b      = (const float*)d_in[9];
    const float* conv_w    = (const float*)d_in[10];
    const float* conv_b    = (const float*)d_in[11];
    const float* na_w      = (const float*)d_in[12];
    const float* na_b      = (const float*)d_in[13];
    const float* q_w       = (const float*)d_in[14];
    const float* k_w       = (const float*)d_in[15];
    const float* v_w       = (const float*)d_in[16];
    const float* cpe_w     = (const float*)d_in[17];
    const float* cpe_b     = (const float*)d_in[18];
    const float* proj_w    = (const float*)d_in[19];
    const float* proj_b    = (const float*)d_in[20];
    const float* norm2_w   = (const float*)d_in[21];
    const float* norm2_b   = (const float*)d_in[22];
    const float* fc1_w     = (const float*)d_in[23];
    const float* fc1_b     = (const float*)d_in[24];
    const float* gnorm_w   = (const float*)d_in[25];
    const float* gnorm_b   = (const float*)d_in[26];
    const float* gconv_w   = (const float*)d_in[27];
    const float* gconv_b   = (const float*)d_in[28];
    const float* fc2_w     = (const float*)d_in[29];
    const float* fc2_b     = (const float*)d_in[30];

    float* S;
    cudaGetSymbolAddress((void**)&S, g_s);
    float* mh   = S + OFF_MH;
    float* mw   = S + OFF_MW;
    float* gh   = S + OFF_GH;
    float* gw   = S + OFF_GW;
    float* res1 = S + OFF_RES1;
    float* ln1  = S + OFF_LN1;
    float* qq   = S + OFF_Q;
    float* r1   = S + OFF_R1;
    float* r2   = S + OFF_R2;
    float* dd   = S + OFF_D;
    float* xa   = S + OFF_XA;
    float* kk   = S + OFF_K;
    float* vt   = S + OFF_VT;
    float* v2   = S + OFF_V2;
    float* ao   = S + OFF_AO;
    float* t2   = S + OFF_T2;
    float* ln2  = S + OFF_LN2;
    float* hbuf = S + OFF_HH;
    float* x2l  = S + OFF_X2;
    float* gt   = S + OFF_GT;
    float* tf   = S + OFF_TF;

    // SDAM
    k_mean<<<Bq * Cq, 64>>>(x, mh, mw);
    k_sdagn<<<dim3(16, Bq, 2), 256>>>(mh, mw, sda_conv_w, sda_gn_w, sda_gn_b, gh, gw);
    k_tokens<<<dim3(128, Bq), dim3(32, 8)>>>(x, gh, gw, norm1_w, norm1_b, res1, ln1);

    // reduced path
    k_red1<<<dim3(256, Bq), 256>>>(ln1, red_w, red_b, r1);
    k_red2<<<dim3(16, Bq), 256>>>(r1, red_w, red_b, r2);
    k_dw3<<<dim3(16, Bq), 256>>>(r2, dw_w, dw_b, dd);
    k_na<<<dim3(16, Bq), 128>>>(dd, conv_w, conv_b, na_w, na_b, xa);
    k_kv<<<dim3(16, Bq), 256>>>(xa, k_w, v_w, kk, vt);
    k_cpe<<<dim3(16, Bq), 256>>>(vt, cpe_w, cpe_b, v2);

    // q projection (M=65536, N=128, K=256)
    k_gemm<0><<<dim3(1, Mrows / 128), 256>>>(ln1, q_w, nullptr, nullptr, qq, Mrows, 128, 256);

    // attention
    k_attn<<<dim3(128, Bq), 256>>>(qq, kk, v2, ao);

    // proj + residual (N=256, K=256)
    k_gemm<5><<<dim3(2, Mrows / 128), 256>>>(ao, proj_w, proj_b, res1, t2, Mrows, 256, 256);

    // MLP
    k_ln<<<Mrows, 256>>>(t2, 256, norm2_w, norm2_b, ln2, 256, 256, 1e-6f);
    k_gemm<3><<<dim3(8, Mrows / 128), 256>>>(ln2, fc1_w, fc1_b, nullptr, hbuf, Mrows, 1024, 256);
    k_ln<<<Mrows, 256>>>(hbuf + 512, 1024, gnorm_w, gnorm_b, x2l, 512, 512, 1e-5f);
    k_gconv<<<dim3(4096, Bq), 256>>>(x2l, hbuf, gconv_w, gconv_b, gt);
    k_gemm<5><<<dim3(2, Mrows / 128), 256>>>(gt, fc2_w, fc2_b, t2, tf, Mrows, 256, 512);

    // output transpose
    k_tr<<<dim3(128, 8, Bq), dim3(32, 8)>>>(tf, (float*)d_out);
}

// round 6
// speedup vs baseline: 1.4696x; 1.4696x over previous
#include <cuda_runtime.h>
#include <math.h>
#include <stdint.h>
#include <mma.h>

using namespace nvcuda;

// ---------------- problem constants ----------------
#define Bq 16
#define Cq 256
#define Hq 64
#define Wq 64
#define Nq 4096
#define NHq 8
#define CRq 128
#define HIDq 1024
#define HALFq 512
#define Mrows (Bq*Nq)      // 65536

// ---------------- scratch layout (floats) ----------------
#define OFF_MH   0ull
#define OFF_MW   262144ull
#define OFF_GH   524288ull
#define OFF_GW   786432ull
#define OFF_RES1 1048576ull
#define OFF_LN1  17825792ull
#define OFF_Q    34603008ull
#define OFF_R1   42991616ull
#define OFF_R2   44040192ull
#define OFF_D    44105728ull
#define OFF_XA   44171264ull
#define OFF_K    44204032ull
#define OFF_VT   44236800ull
#define OFF_V2   44302336ull
#define OFF_AO   44367872ull
#define OFF_T2   61145088ull
#define OFF_LN2  77922304ull
#define OFF_HH   94699520ull
#define OFF_X2   161808384ull
#define OFF_GT   195362816ull
#define OFF_TF   228917248ull
#define OFF_WTQ  245694464ull
#define OFF_WTP  245727232ull
#define OFF_WT1  245792768ull
#define OFF_WT2  246054912ull
#define G_TOTAL  246185984ull

static __device__ float g_s[G_TOTAL];

#define DINL __device__ __forceinline__

DINL float gelu_f(float x) { return 0.5f * x * (1.0f + erff(x * 0.70710678118654752f)); }

DINL void blockReduce2(float& s, float& q, float* sh) {
    int lane = threadIdx.x & 31, wid = threadIdx.x >> 5;
#pragma unroll
    for (int o = 16; o > 0; o >>= 1) {
        s += __shfl_down_sync(0xffffffffu, s, o);
        q += __shfl_down_sync(0xffffffffu, q, o);
    }
    if (lane == 0) { sh[wid] = s; sh[32 + wid] = q; }
    __syncthreads();
    if (threadIdx.x == 0) {
        float ss = 0.f, qq = 0.f;
        int nw = blockDim.x >> 5;
        for (int i = 0; i < nw; i++) { ss += sh[i]; qq += sh[32 + i]; }
        sh[0] = ss; sh[32] = qq;
    }
    __syncthreads();
    s = sh[0]; q = sh[32];
}

// ================= wmma tf32 GEMM =================
// C[M,N] = A[M,K] @ BT[N,K]^T  (BT pre-transposed, K-major)
// OP bits: 1=bias, 2=gelu, 4=residual.
// CTA tile 128x128, K-chunk 32, 128 threads (4 warps, each 64x64), cp.async 2-stage.
#define LDP 36                     // padded row (floats) for 32-float k-rows
#define STAGE_F (128*LDP*2)        // floats per stage (A + B) = 9216
#define DSMB (2*STAGE_F*4)         // 73728 bytes

template <int OP>
__global__ __launch_bounds__(128) void k_tc_gemm(const float* __restrict__ A,
        const float* __restrict__ BT, const float* __restrict__ bias,
        const float* __restrict__ res, float* __restrict__ C, int M, int N, int K) {
    extern __shared__ __align__(16) char dsm[];
    float* dsmf = (float*)dsm;
    __shared__ float sbias[128];
    int tid = threadIdx.x;
    int m0 = blockIdx.y << 7, n0 = blockIdx.x << 7;
    if (OP & 1) sbias[tid] = bias[n0 + tid];

    int w = tid >> 5;
    int wm = w >> 1, wn = w & 1;    // 2x2 warps, each 64x64

    wmma::fragment<wmma::accumulator, 16, 16, 8, float> acc[4][4];
#pragma unroll
    for (int mi = 0; mi < 4; mi++)
#pragma unroll
        for (int ni = 0; ni < 4; ni++) wmma::fill_fragment(acc[mi][ni], 0.f);

    // loader mapping: 16B segment c4 (0..7) within 128B k-row, rows r0+16*it
    int c4 = tid & 7, r0 = tid >> 3;
    const float* Ag = A + (size_t)(m0 + r0) * K + c4 * 4;
    const float* Bg = BT + (size_t)(n0 + r0) * K + c4 * 4;
    int nk = K >> 5;

#define ISSUE_CHUNK(i)                                                             \
    {                                                                              \
        uint32_t sa = (uint32_t)__cvta_generic_to_shared(                          \
            dsmf + ((i) & 1) * STAGE_F) + (uint32_t)(r0 * (LDP * 4) + c4 * 16);    \
        uint32_t sb = sa + (uint32_t)(128 * LDP * 4);                              \
        const float* ga = Ag + (i) * 32;                                           \
        const float* gb = Bg + (i) * 32;                                           \
        _Pragma("unroll")                                                          \
        for (int it = 0; it < 8; it++)                                             \
            asm volatile("cp.async.cg.shared.global [%0], [%1], 16;"               \
                :: "r"(sa + it * (16u * LDP * 4)), "l"(ga + (size_t)it * 16 * K)   \
                : "memory");                                                       \
        _Pragma("unroll")                                                          \
        for (int it = 0; it < 8; it++)                                             \
            asm volatile("cp.async.cg.shared.global [%0], [%1], 16;"               \
                :: "r"(sb + it * (16u * LDP * 4)), "l"(gb + (size_t)it * 16 * K)   \
                : "memory");                                                       \
        asm volatile("cp.async.commit_group;");                                    \
    }

    ISSUE_CHUNK(0);
    for (int i = 0; i < nk; i++) {
        if (i + 1 < nk) {
            ISSUE_CHUNK(i + 1);
            asm volatile("cp.async.wait_group 1;");
        } else {
            asm volatile("cp.async.wait_group 0;");
        }
        __syncthreads();
        const float* As = dsmf + (i & 1) * STAGE_F;
        const float* Bs = As + 128 * LDP;
#pragma unroll
        for (int kk = 0; kk < 32; kk += 8) {
            wmma::fragment<wmma::matrix_a, 16, 16, 8, wmma::precision::tf32, wmma::row_major> af[4];
            wmma::fragment<wmma::matrix_b, 16, 16, 8, wmma::precision::tf32, wmma::col_major> bf[4];
#pragma unroll
            for (int mi = 0; mi < 4; mi++) {
                wmma::load_matrix_sync(af[mi], As + (wm * 64 + mi * 16) * LDP + kk, LDP);
#pragma unroll
                for (int t = 0; t < af[mi].num_elements; t++)
                    af[mi].x[t] = wmma::__float_to_tf32(af[mi].x[t]);
            }
#pragma unroll
            for (int ni = 0; ni < 4; ni++) {
                wmma::load_matrix_sync(bf[ni], Bs + (wn * 64 + ni * 16) * LDP + kk, LDP);
#pragma unroll
                for (int t = 0; t < bf[ni].num_elements; t++)
                    bf[ni].x[t] = wmma::__float_to_tf32(bf[ni].x[t]);
            }
#pragma unroll
            for (int mi = 0; mi < 4; mi++)
#pragma unroll
                for (int ni = 0; ni < 4; ni++)
                    wmma::mma_sync(acc[mi][ni], af[mi], bf[ni], acc[mi][ni]);
        }
        __syncthreads();
    }

    // stage accumulators to smem (reuse stage buffers), then coalesced epilogue
    float* Cs = dsmf;
#pragma unroll
    for (int mi = 0; mi < 4; mi++)
#pragma unroll
        for (int ni = 0; ni < 4; ni++)
            wmma::store_matrix_sync(Cs + (wm * 64 + mi * 16) * 132 + wn * 64 + ni * 16,
                                    acc[mi][ni], 132, wmma::mem_row_major);
    __syncthreads();

    float* Cp = C + (size_t)m0 * N + n0 + tid;
    const float* Rp = res + (size_t)m0 * N + n0 + tid;
#pragma unroll 4
    for (int r = 0; r < 128; r++) {
        float v = Cs[r * 132 + tid];
        if (OP & 1) v += sbias[tid];
        if (OP & 2) v = gelu_f(v);
        if (OP & 4) v += Rp[(size_t)r * N];
        Cp[(size_t)r * N] = v;
    }
}

// weight transpose: w[K,N] -> wt[N,K]
__global__ void k_wt(const float* __restrict__ w, float* __restrict__ wt, int K, int N) {
    __shared__ float t[32][33];
    int nb = blockIdx.x * 32, kb = blockIdx.y * 32;
    int tx = threadIdx.x, ty = threadIdx.y;
#pragma unroll
    for (int j = 0; j < 4; j++)
        t[ty + j * 8][tx] = w[(size_t)(kb + ty + j * 8) * N + nb + tx];
    __syncthreads();
#pragma unroll
    for (int j = 0; j < 4; j++)
        wt[(size_t)(nb + ty + j * 8) * K + kb + tx] = t[tx][ty + j * 8];
}

// ---------------- K1: coordinate pooled means ----------------
__global__ void k_mean(const float* __restrict__ x, float* __restrict__ mh, float* __restrict__ mw) {
    int bc = blockIdx.x;
    const float* p = x + (size_t)bc * 4096;
    int w = threadIdx.x;
    __shared__ float part[128];
    float colsum = 0.f;
    for (int r = 0; r < 64; r++) {
        float v = p[r * 64 + w];
        colsum += v;
        float s = v;
#pragma unroll
        for (int o = 16; o > 0; o >>= 1) s += __shfl_down_sync(0xffffffffu, s, o);
        if ((w & 31) == 0) part[(w >> 5) * 64 + r] = s;
    }
    __syncthreads();
    mh[(size_t)bc * 64 + w] = (part[w] + part[64 + w]) * (1.f / 64.f);
    mw[(size_t)bc * 64 + w] = colsum * (1.f / 64.f);
}

// ---------------- K2: dwconv1d(k=7) + GroupNorm(16) + ReLU ----------------
__global__ void k_sdagn(const float* __restrict__ mh, const float* __restrict__ mw,
                        const float* __restrict__ w7, const float* __restrict__ gnw,
                        const float* __restrict__ gnb, float* __restrict__ gh, float* __restrict__ gw_) {
    int grp = blockIdx.x, b = blockIdx.y;
    const float* mean = (blockIdx.z ? mw : mh) + (size_t)b * Cq * 64;
    float* out = (blockIdx.z ? gw_ : gh) + (size_t)b * Cq * 64;
    __shared__ float buf[1024];
    __shared__ float sh[64];
    int tid = threadIdx.x;
    float ls = 0.f, lq = 0.f;
#pragma unroll
    for (int j = 0; j < 4; j++) {
        int idx = tid + j * 256;
        int c = grp * 16 + (idx >> 6), l = idx & 63;
        const float* m = mean + c * 64;
        float acc = 0.f;
#pragma unroll
        for (int k = 0; k < 7; k++) {
            int ll = l + k - 3;
            if (ll >= 0 && ll < 64) acc += m[ll] * w7[c * 7 + k];
        }
        buf[idx] = acc; ls += acc; lq += acc * acc;
    }
    blockReduce2(ls, lq, sh);
    float mu = ls * (1.f / 1024.f);
    float rstd = rsqrtf(lq * (1.f / 1024.f) - mu * mu + 1e-5f);
#pragma unroll
    for (int j = 0; j < 4; j++) {
        int idx = tid + j * 256;
        int c = grp * 16 + (idx >> 6), l = idx & 63;
        float y = (buf[idx] - mu) * rstd * gnw[c] + gnb[c];
        out[(size_t)c * 64 + l] = fmaxf(y, 0.f);
    }
}

// ---------------- K3: modulate + to tokens + LN1 ----------------
__global__ void k_tokens(const float* __restrict__ x, const float* __restrict__ gh,
                         const float* __restrict__ gw_, const float* __restrict__ n1w,
                         const float* __restrict__ n1b, float* __restrict__ res, float* __restrict__ ln) {
    int b = blockIdx.y;
    int n0 = blockIdx.x * 32;
    int h = n0 >> 6, w0 = n0 & 63;
    int nx = threadIdx.x, cy = threadIdx.y;
    __shared__ float tile[256][33];
    __shared__ float mu[32], rs[32];
    const float* ghb = gh + (size_t)b * Cq * 64;
    const float* gwb = gw_ + (size_t)b * Cq * 64;
    const float* xb = x + (size_t)b * Cq * Nq;
#pragma unroll 4
    for (int j = 0; j < 32; j++) {
        int c = cy * 32 + j;
        float v = xb[(size_t)c * Nq + h * 64 + w0 + nx] * ghb[c * 64 + h] * gwb[c * 64 + w0 + nx];
        tile[c][nx] = v;
    }
    __syncthreads();
    int tid = cy * 32 + nx, lane = tid & 31, warp = tid >> 5;
    for (int nn = warp; nn < 32; nn += 8) {
        float s = 0.f, q = 0.f;
        for (int c = lane; c < 256; c += 32) { float v = tile[c][nn]; s += v; q += v * v; }
#pragma unroll
        for (int o = 16; o > 0; o >>= 1) {
            s += __shfl_down_sync(0xffffffffu, s, o);
            q += __shfl_down_sync(0xffffffffu, q, o);
        }
        if (lane == 0) {
            float m = s * (1.f / 256.f);
            mu[nn] = m; rs[nn] = rsqrtf(q * (1.f / 256.f) - m * m + 1e-6f);
        }
    }
    __syncthreads();
    float* resp = res + ((size_t)b * Nq + n0) * Cq;
    float* lnp = ln + ((size_t)b * Nq + n0) * Cq;
    for (int idx = tid; idx < 32 * 256; idx += 256) {
        int nl = idx >> 8, c = idx & 255;
        float v = tile[c][nl];
        resp[(size_t)nl * 256 + c] = v;
        lnp[(size_t)nl * 256 + c] = (v - mu[nl]) * rs[nl] * n1w[c] + n1b[c];
    }
}

// ---------------- reduction path ----------------
__global__ void k_red1(const float* __restrict__ ln1, const float* __restrict__ rw,
                       const float* __restrict__ rb, float* __restrict__ r1) {
    int p = blockIdx.x, b = blockIdx.y, c = threadIdx.x;
    int i = p >> 4, j = p & 15;
    float acc = rb[c];
    const float* base = ln1 + (size_t)b * Nq * Cq + c;
#pragma unroll
    for (int a = 0; a < 4; a++)
#pragma unroll
        for (int d = 0; d < 4; d++) {
            int n = (4 * i + a) * 64 + 4 * j + d;
            acc += base[(size_t)n * 256] * rw[c * 16 + a * 4 + d];
        }
    r1[((size_t)b * 256 + p) * 256 + c] = acc;
}

__global__ void k_red2(const float* __restrict__ r1, const float* __restrict__ rw,
                       const float* __restrict__ rb, float* __restrict__ r2) {
    int p2 = blockIdx.x, b = blockIdx.y, c = threadIdx.x;
    int i2 = p2 >> 2, j2 = p2 & 3;
    float acc = rb[c];
#pragma unroll
    for (int a = 0; a < 4; a++)
#pragma unroll
        for (int d = 0; d < 4; d++) {
            int p = (4 * i2 + a) * 16 + (4 * j2 + d);
            acc += r1[((size_t)b * 256 + p) * 256 + c] * rw[c * 16 + a * 4 + d];
        }
    r2[((size_t)b * 16 + p2) * 256 + c] = acc;
}

__global__ void k_dw3(const float* __restrict__ r2, const float* __restrict__ dww,
                      const float* __restrict__ dwb, float* __restrict__ dd) {
    int p = blockIdx.x, b = blockIdx.y, c = threadIdx.x;
    int i = p >> 2, j = p & 3;
    float acc = dwb[c];
#pragma unroll
    for (int a = 0; a < 3; a++) {
        int ii = i + a - 1;
        if (ii < 0 || ii >= 4) continue;
#pragma unroll
        for (int d = 0; d < 3; d++) {
            int jj = j + d - 1;
            if (jj < 0 || jj >= 4) continue;
            acc += r2[((size_t)b * 16 + ii * 4 + jj) * 256 + c] * dww[c * 9 + a * 3 + d];
        }
    }
    dd[((size_t)b * 16 + p) * 256 + c] = acc;
}

__global__ void k_na(const float* __restrict__ dd, const float* __restrict__ cw,
                     const float* __restrict__ cb, const float* __restrict__ naw,
                     const float* __restrict__ nab, float* __restrict__ xa) {
    int p = blockIdx.x, b = blockIdx.y, o = threadIdx.x;
    __shared__ float ds[256];
    __shared__ float sh[64];
    const float* dp = dd + ((size_t)b * 16 + p) * 256;
    ds[o] = dp[o]; ds[o + 128] = dp[o + 128];
    __syncthreads();
    float e = cb[o];
    for (int c = 0; c < 256; c++) e += ds[c] * cw[o * 256 + c];
    float s = e, q = e * e;
    blockReduce2(s, q, sh);
    float mu = s * (1.f / 128.f);
    float rstd = rsqrtf(q * (1.f / 128.f) - mu * mu + 1e-5f);
    float y = (e - mu) * rstd * naw[o] + nab[o];
    xa[((size_t)b * 16 + p) * 128 + o] = gelu_f(y);
}

__global__ void k_kv(const float* __restrict__ xa, const float* __restrict__ kw,
                     const float* __restrict__ vw, float* __restrict__ kk, float* __restrict__ vt) {
    int p = blockIdx.x, b = blockIdx.y, t = threadIdx.x;
    __shared__ float xs[128];
    if (t < 128) xs[t] = xa[((size_t)b * 16 + p) * 128 + t];
    __syncthreads();
    if (t < 128) {
        float a = 0.f;
        for (int c = 0; c < 128; c++) a += xs[c] * kw[c * 128 + t];
        kk[((size_t)b * 16 + p) * 128 + t] = a;
    }
    float a2 = 0.f;
    for (int c = 0; c < 128; c++) a2 += xs[c] * vw[c * 256 + t];
    vt[((size_t)b * 16 + p) * 256 + t] = a2;
}

__global__ void k_cpe(const float* __restrict__ vt, const float* __restrict__ cw,
                      const float* __restrict__ cb, float* __restrict__ v2) {
    int p = blockIdx.x, b = blockIdx.y, ch = threadIdx.x;
    int i = p >> 2, j = p & 3;
    float acc = cb[ch];
#pragma unroll
    for (int a = 0; a < 3; a++) {
        int ii = i + a - 1;
        if (ii < 0 || ii >= 4) continue;
#pragma unroll
        for (int d = 0; d < 3; d++) {
            int jj = j + d - 1;
            if (jj < 0 || jj >= 4) continue;
            acc += vt[((size_t)b * 16 + ii * 4 + jj) * 256 + ch] * cw[ch * 9 + a * 3 + d];
        }
    }
    v2[((size_t)b * 16 + p) * 256 + ch] = vt[((size_t)b * 16 + p) * 256 + ch] + acc;
}

// ---------------- fused attention ----------------
__global__ void k_attn(const float* __restrict__ q, const float* __restrict__ kk,
                       const float* __restrict__ v2, float* __restrict__ ao) {
    __shared__ float ks[8 * 260];
    __shared__ float vs[8 * 516];
    int b = blockIdx.y;
    int tid = threadIdx.x;
    for (int idx = tid; idx < 2048; idx += 256) {
        int head = idx >> 8, r = idx & 255, m = r >> 4, i = r & 15;
        ks[head * 260 + m * 16 + i] = kk[((size_t)b * 16 + m) * 128 + head * 16 + i];
    }
    for (int idx = tid; idx < 4096; idx += 256) {
        int head = idx >> 9, r = idx & 511, m = r >> 5, d = r & 31;
        vs[head * 516 + m * 32 + d] = v2[((size_t)b * 16 + m) * 256 + head * 32 + d];
    }
    __syncthreads();
    int nl = tid >> 3, head = tid & 7;
    int n = blockIdx.x * 32 + nl;
    const float* qp = q + ((size_t)b * Nq + n) * 128 + head * 16;
    float qr[16];
#pragma unroll
    for (int i = 0; i < 16; i++) qr[i] = qp[i];
    const float* kh = ks + head * 260;
    float s[16];
    float mx = -1e30f;
#pragma unroll
    for (int m = 0; m < 16; m++) {
        float a = 0.f;
#pragma unroll
        for (int i = 0; i < 16; i++) a += qr[i] * kh[m * 16 + i];
        a *= 0.25f;
        s[m] = a;
        mx = fmaxf(mx, a);
    }
    float sum = 0.f;
#pragma unroll
    for (int m = 0; m < 16; m++) { s[m] = __expf(s[m] - mx); sum += s[m]; }
    float inv = 1.f / sum;
    float o[32];
#pragma unroll
    for (int d = 0; d < 32; d++) o[d] = 0.f;
    const float* vh = vs + head * 516;
#pragma unroll
    for (int m = 0; m < 16; m++) {
        float pm = s[m] * inv;
#pragma unroll
        for (int d = 0; d < 32; d++) o[d] += pm * vh[m * 32 + d];
    }
    float* op = ao + ((size_t)b * Nq + n) * 256 + head * 32;
#pragma unroll
    for (int d = 0; d < 32; d++) op[d] = o[d];
}

// ---------------- LayerNorm ----------------
__global__ void k_ln(const float* __restrict__ in, int istr, const float* __restrict__ w,
                     const float* __restrict__ b, float* __restrict__ out, int ostr, int D, float eps) {
    size_t row = blockIdx.x;
    const float* ip = in + row * (size_t)istr;
    int cnt = D >> 8;
    float v[2];
    float s = 0.f, q = 0.f;
    for (int j = 0; j < cnt; j++) {
        float x = ip[threadIdx.x + j * 256];
        v[j] = x; s += x; q += x * x;
    }
    __shared__ float sh[64];
    blockReduce2(s, q, sh);
    float mu = s / (float)D;
    float rstd = rsqrtf(q / (float)D - mu * mu + eps);
    float* op = out + row * (size_t)ostr;
    for (int j = 0; j < cnt; j++) {
        int c = threadIdx.x + j * 256;
        op[c] = (v[j] - mu) * rstd * w[c] + b[c];
    }
}

// ---------------- depthwise 3x3 gate conv + multiply ----------------
__global__ void k_gconv(const float* __restrict__ x2, const float* __restrict__ hbuf,
                        const float* __restrict__ gcw, const float* __restrict__ gcb,
                        float* __restrict__ gated) {
    int n = blockIdx.x, b = blockIdx.y;
    int hh = n >> 6, ww = n & 63;
    const float* xb = x2 + (size_t)b * Nq * 512;
#pragma unroll
    for (int r = 0; r < 2; r++) {
        int ch = threadIdx.x + r * 256;
        float acc = gcb[ch];
#pragma unroll
        for (int a = 0; a < 3; a++) {
            int hi = hh + a - 1;
            if (hi < 0 || hi >= 64) continue;
#pragma unroll
            for (int d = 0; d < 3; d++) {
                int wi = ww + d - 1;
                if (wi < 0 || wi >= 64) continue;
                acc += xb[(size_t)(hi * 64 + wi) * 512 + ch] * gcw[ch * 9 + a * 3 + d];
            }
        }
        float x1 = hbuf[((size_t)b * Nq + n) * 1024 + ch];
        gated[((size_t)b * Nq + n) * 512 + ch] = x1 * acc;
    }
}

// ---------------- final transpose ----------------
__global__ void k_tr(const float* __restrict__ tf, float* __restrict__ out) {
    __shared__ float t[32][33];
    int n0 = blockIdx.x * 32, c0 = blockIdx.y * 32, b = blockIdx.z;
    const float* ip = tf + (size_t)b * Nq * Cq;
    float* op = out + (size_t)b * Cq * Nq;
#pragma unroll
    for (int j = 0; j < 4; j++) {
        int i = threadIdx.y + j * 8;
        t[i][threadIdx.x] = ip[(size_t)(n0 + i) * 256 + c0 + threadIdx.x];
    }
    __syncthreads();
#pragma unroll
    for (int j = 0; j < 4; j++) {
        int i = threadIdx.y + j * 8;
        op[(size_t)(c0 + i) * 4096 + n0 + threadIdx.x] = t[threadIdx.x][i];
    }
}

// ---------------- host launch ----------------
extern "C" void kernel_launch(void* const* d_in, const int* in_sizes, int n_in,
                              void* d_out, int out_size) {
    const float* x          = (const float*)d_in[0];
    const float* sda_conv_w = (const float*)d_in[1];
    const float* sda_gn_w   = (const float*)d_in[2];
    const float* sda_gn_b   = (const float*)d_in[3];
    const float* norm1_w    = (const float*)d_in[4];
    const float* norm1_b    = (const float*)d_in[5];
    const float* red_w      = (const float*)d_in[6];
    const float* red_b      = (const float*)d_in[7];
    const float* dw_w       = (const float*)d_in[8];
    const float* dw_b       = (const float*)d_in[9];
    const float* conv_w     = (const float*)d_in[10];
    const float* conv_b     = (const float*)d_in[11];
    const float* na_w       = (const float*)d_in[12];
    const float* na_b       = (const float*)d_in[13];
    const float* q_w        = (const float*)d_in[14];
    const float* k_w        = (const float*)d_in[15];
    const float* v_w        = (const float*)d_in[16];
    const float* cpe_w      = (const float*)d_in[17];
    const float* cpe_b      = (const float*)d_in[18];
    const float* proj_w     = (const float*)d_in[19];
    const float* proj_b     = (const float*)d_in[20];
    const float* norm2_w    = (const float*)d_in[21];
    const float* norm2_b    = (const float*)d_in[22];
    const float* fc1_w      = (const float*)d_in[23];
    const float* fc1_b      = (const float*)d_in[24];
    const float* gnorm_w    = (const float*)d_in[25];
    const float* gnorm_b    = (const float*)d_in[26];
    const float* gconv_w    = (const float*)d_in[27];
    const float* gconv_b    = (const float*)d_in[28];
    const float* fc2_w      = (const float*)d_in[29];
    const float* fc2_b      = (const float*)d_in[30];

    float* S;
    cudaGetSymbolAddress((void**)&S, g_s);
    float* mh   = S + OFF_MH;
    float* mw   = S + OFF_MW;
    float* gh   = S + OFF_GH;
    float* gw   = S + OFF_GW;
    float* res1 = S + OFF_RES1;
    float* ln1  = S + OFF_LN1;
    float* qq   = S + OFF_Q;
    float* r1   = S + OFF_R1;
    float* r2   = S + OFF_R2;
    float* dd   = S + OFF_D;
    float* xa   = S + OFF_XA;
    float* kk   = S + OFF_K;
    float* vt   = S + OFF_VT;
    float* v2   = S + OFF_V2;
    float* ao   = S + OFF_AO;
    float* t2   = S + OFF_T2;
    float* ln2  = S + OFF_LN2;
    float* hbuf = S + OFF_HH;
    float* x2l  = S + OFF_X2;
    float* gt   = S + OFF_GT;
    float* tf   = S + OFF_TF;
    float* wtq  = S + OFF_WTQ;
    float* wtp  = S + OFF_WTP;
    float* wt1  = S + OFF_WT1;
    float* wt2  = S + OFF_WT2;

    cudaFuncSetAttribute(k_tc_gemm<0>, cudaFuncAttributeMaxDynamicSharedMemorySize, DSMB);
    cudaFuncSetAttribute(k_tc_gemm<3>, cudaFuncAttributeMaxDynamicSharedMemorySize, DSMB);
    cudaFuncSetAttribute(k_tc_gemm<5>, cudaFuncAttributeMaxDynamicSharedMemorySize, DSMB);

    // weight transposes (K-major layout for GEMM B operand)
    k_wt<<<dim3(4, 8), dim3(32, 8)>>>(q_w, wtq, 256, 128);
    k_wt<<<dim3(8, 8), dim3(32, 8)>>>(proj_w, wtp, 256, 256);
    k_wt<<<dim3(32, 8), dim3(32, 8)>>>(fc1_w, wt1, 256, 1024);
    k_wt<<<dim3(8, 16), dim3(32, 8)>>>(fc2_w, wt2, 512, 256);

    // SDAM
    k_mean<<<Bq * Cq, 64>>>(x, mh, mw);
    k_sdagn<<<dim3(16, Bq, 2), 256>>>(mh, mw, sda_conv_w, sda_gn_w, sda_gn_b, gh, gw);
    k_tokens<<<dim3(128, Bq), dim3(32, 8)>>>(x, gh, gw, norm1_w, norm1_b, res1, ln1);

    // reduced path
    k_red1<<<dim3(256, Bq), 256>>>(ln1, red_w, red_b, r1);
    k_red2<<<dim3(16, Bq), 256>>>(r1, red_w, red_b, r2);
    k_dw3<<<dim3(16, Bq), 256>>>(r2, dw_w, dw_b, dd);
    k_na<<<dim3(16, Bq), 128>>>(dd, conv_w, conv_b, na_w, na_b, xa);
    k_kv<<<dim3(16, Bq), 256>>>(xa, k_w, v_w, kk, vt);
    k_cpe<<<dim3(16, Bq), 256>>>(vt, cpe_w, cpe_b, v2);

    // q projection (M=65536, N=128, K=256)
    k_tc_gemm<0><<<dim3(1, Mrows / 128), 128, DSMB>>>(ln1, wtq, nullptr, nullptr, qq, Mrows, 128, 256);

    // attention
    k_attn<<<dim3(128, Bq), 256>>>(qq, kk, v2, ao);

    // proj + bias + residual
    k_tc_gemm<5><<<dim3(2, Mrows / 128), 128, DSMB>>>(ao, wtp, proj_b, res1, t2, Mrows, 256, 256);

    // MLP
    k_ln<<<Mrows, 256>>>(t2, 256, norm2_w, norm2_b, ln2, 256, 256, 1e-6f);
    k_tc_gemm<3><<<dim3(8, Mrows / 128), 128, DSMB>>>(ln2, wt1, fc1_b, nullptr, hbuf, Mrows, 1024, 256);
    k_ln<<<Mrows, 256>>>(hbuf + 512, 1024, gnorm_w, gnorm_b, x2l, 512, 512, 1e-5f);
    k_gconv<<<dim3(4096, Bq), 256>>>(x2l, hbuf, gconv_w, gconv_b, gt);
    k_tc_gemm<5><<<dim3(2, Mrows / 128), 128, DSMB>>>(gt, wt2, fc2_b, t2, tf, Mrows, 256, 512);

    // output transpose
    k_tr<<<dim3(128, 8, Bq), dim3(32, 8)>>>(tf, (float*)d_out);
}

// round 7
// speedup vs baseline: 2.2293x; 1.5170x over previous
#include <cuda_runtime.h>
#include <cuda_bf16.h>
#include <math.h>
#include <stdint.h>
#include <mma.h>

using namespace nvcuda;

// ---------------- problem constants ----------------
#define Bq 16
#define Cq 256
#define Hq 64
#define Wq 64
#define Nq 4096
#define NHq 8
#define CRq 128
#define HIDq 1024
#define HALFq 512
#define Mrows (Bq*Nq)      // 65536

// ---------------- scratch layout (float units) ----------------
#define OFF_MH    0ull
#define OFF_MW    262144ull
#define OFF_GH    524288ull
#define OFF_GW    786432ull
#define OFF_RES1  1048576ull
#define OFF_LNB   17825792ull     // bf16 [M,256]
#define OFF_Q     26214400ull     // f32  [M,128]
#define OFF_R1    34603008ull
#define OFF_R2    35651584ull
#define OFF_D     35717120ull
#define OFF_XA    35782656ull
#define OFF_K     35815424ull
#define OFF_VT    35848192ull
#define OFF_V2    35913728ull
#define OFF_AOB   35979264ull     // bf16 [M,256]
#define OFF_T2    44367872ull     // f32  [M,256]
#define OFF_LN2B  61145088ull     // bf16 [M,256]
#define OFF_HH    69533696ull     // f32  [M,1024]
#define OFF_X2B   136642560ull    // bf16 [M,512]
#define OFF_GTB   153419776ull    // bf16 [M,512]
#define OFF_TF    170196992ull    // f32  [M,256]
#define OFF_WTQ   186974208ull    // bf16 [128,256]
#define OFF_WTP   186990592ull    // bf16 [256,256]
#define OFF_WT1   187023360ull    // bf16 [1024,256]
#define OFF_WT2   187154432ull    // bf16 [256,512]
#define G_TOTAL   187219968ull

static __device__ float g_s[G_TOTAL];

#define DINL __device__ __forceinline__

DINL float gelu_f(float x) { return 0.5f * x * (1.0f + erff(x * 0.70710678118654752f)); }
DINL __nv_bfloat16 f2b(float x) { return __float2bfloat16_rn(x); }

DINL void blockReduce2(float& s, float& q, float* sh) {
    int lane = threadIdx.x & 31, wid = threadIdx.x >> 5;
#pragma unroll
    for (int o = 16; o > 0; o >>= 1) {
        s += __shfl_down_sync(0xffffffffu, s, o);
        q += __shfl_down_sync(0xffffffffu, q, o);
    }
    if (lane == 0) { sh[wid] = s; sh[32 + wid] = q; }
    __syncthreads();
    if (threadIdx.x == 0) {
        float ss = 0.f, qq = 0.f;
        int nw = blockDim.x >> 5;
        for (int i = 0; i < nw; i++) { ss += sh[i]; qq += sh[32 + i]; }
        sh[0] = ss; sh[32] = qq;
    }
    __syncthreads();
    s = sh[0]; q = sh[32];
}

// ================= wmma bf16 GEMM =================
// C[M,N] = A[M,K] @ BT[N,K]^T  (A, BT bf16 K-major; C f32)
// OP bits: 1=bias, 2=gelu, 4=residual.
// CTA 128x128, K-chunk 64, 256 threads (8 warps, 2x4, each 64x32), 2-stage cp.async.
#define LDE 72                      // padded row in bf16 elems (64 data + 8 pad = 144B)
#define STAGE_E (128*LDE*2)         // bf16 elems per stage (A + B) = 18432
#define DSMB (2*STAGE_E*2)          // 73728 bytes

template <int OP>
__global__ __launch_bounds__(256) void k_bf_gemm(const __nv_bfloat16* __restrict__ A,
        const __nv_bfloat16* __restrict__ BT, const float* __restrict__ bias,
        const float* __restrict__ res, float* __restrict__ C, int M, int N, int K) {
    extern __shared__ __align__(16) char dsm[];
    __nv_bfloat16* sm = (__nv_bfloat16*)dsm;
    __shared__ float sbias[128];
    int tid = threadIdx.x;
    int m0 = blockIdx.y << 7, n0 = blockIdx.x << 7;
    if ((OP & 1) && tid < 128) sbias[tid] = bias[n0 + tid];

    int w = tid >> 5;
    int wm = w >> 2, wn = w & 3;    // 2x4 warps: 64-row x 32-col tiles

    wmma::fragment<wmma::accumulator, 16, 16, 16, float> acc[4][2];
#pragma unroll
    for (int mi = 0; mi < 4; mi++)
#pragma unroll
        for (int ni = 0; ni < 2; ni++) wmma::fill_fragment(acc[mi][ni], 0.f);

    // loader: 16B segment c4 (0..7) within 128B k-row; rows r0+32*it
    int c4 = tid & 7, r0 = tid >> 3;
    const __nv_bfloat16* Ag = A + (size_t)(m0 + r0) * K + c4 * 8;
    const __nv_bfloat16* Bg = BT + (size_t)(n0 + r0) * K + c4 * 8;
    int nk = K >> 6;

#define ISSUE_CHUNK(i)                                                              \
    {                                                                               \
        uint32_t sa = (uint32_t)__cvta_generic_to_shared(sm) +                      \
            (uint32_t)(((i) & 1) * (STAGE_E * 2)) + (uint32_t)(r0 * 144 + c4 * 16); \
        uint32_t sb = sa + (uint32_t)(128 * 144);                                   \
        const __nv_bfloat16* ga = Ag + (i) * 64;                                    \
        const __nv_bfloat16* gb = Bg + (i) * 64;                                    \
        _Pragma("unroll")                                                           \
        for (int it = 0; it < 4; it++)                                              \
            asm volatile("cp.async.cg.shared.global [%0], [%1], 16;"                \
                :: "r"(sa + it * (32u * 144u)), "l"(ga + (size_t)it * 32 * K)       \
                : "memory");                                                        \
        _Pragma("unroll")                                                           \
        for (int it = 0; it < 4; it++)                                              \
            asm volatile("cp.async.cg.shared.global [%0], [%1], 16;"                \
                :: "r"(sb + it * (32u * 144u)), "l"(gb + (size_t)it * 32 * K)       \
                : "memory");                                                        \
        asm volatile("cp.async.commit_group;");                                     \
    }

    ISSUE_CHUNK(0);
    for (int i = 0; i < nk; i++) {
        if (i + 1 < nk) {
            ISSUE_CHUNK(i + 1);
            asm volatile("cp.async.wait_group 1;");
        } else {
            asm volatile("cp.async.wait_group 0;");
        }
        __syncthreads();
        const __nv_bfloat16* As = sm + (i & 1) * STAGE_E;
        const __nv_bfloat16* Bs = As + 128 * LDE;
#pragma unroll
        for (int kk = 0; kk < 64; kk += 16) {
            wmma::fragment<wmma::matrix_a, 16, 16, 16, __nv_bfloat16, wmma::row_major> af[4];
            wmma::fragment<wmma::matrix_b, 16, 16, 16, __nv_bfloat16, wmma::col_major> bf[2];
#pragma unroll
            for (int mi = 0; mi < 4; mi++)
                wmma::load_matrix_sync(af[mi], As + (wm * 64 + mi * 16) * LDE + kk, LDE);
#pragma unroll
            for (int ni = 0; ni < 2; ni++)
                wmma::load_matrix_sync(bf[ni], Bs + (wn * 32 + ni * 16) * LDE + kk, LDE);
#pragma unroll
            for (int mi = 0; mi < 4; mi++)
#pragma unroll
                for (int ni = 0; ni < 2; ni++)
                    wmma::mma_sync(acc[mi][ni], af[mi], bf[ni], acc[mi][ni]);
        }
        __syncthreads();
    }

    // stage accumulators to smem (reuse stage buffers), then coalesced epilogue
    float* Cs = (float*)dsm;
#pragma unroll
    for (int mi = 0; mi < 4; mi++)
#pragma unroll
        for (int ni = 0; ni < 2; ni++)
            wmma::store_matrix_sync(Cs + (wm * 64 + mi * 16) * 132 + wn * 32 + ni * 16,
                                    acc[mi][ni], 132, wmma::mem_row_major);
    __syncthreads();

    int col = tid & 127, rr = tid >> 7;
    float* Cp = C + (size_t)m0 * N + n0 + col;
    const float* Rp = res + (size_t)m0 * N + n0 + col;
#pragma unroll 4
    for (int r = rr; r < 128; r += 2) {
        float v = Cs[r * 132 + col];
        if (OP & 1) v += sbias[col];
        if (OP & 2) v = gelu_f(v);
        if (OP & 4) v += Rp[(size_t)r * N];
        Cp[(size_t)r * N] = v;
    }
}

// weight transpose + bf16 convert: w[K,N] -> wt[N,K] bf16
__global__ void k_wt(const float* __restrict__ w, __nv_bfloat16* __restrict__ wt, int K, int N) {
    __shared__ float t[32][33];
    int nb = blockIdx.x * 32, kb = blockIdx.y * 32;
    int tx = threadIdx.x, ty = threadIdx.y;
#pragma unroll
    for (int j = 0; j < 4; j++)
        t[ty + j * 8][tx] = w[(size_t)(kb + ty + j * 8) * N + nb + tx];
    __syncthreads();
#pragma unroll
    for (int j = 0; j < 4; j++)
        wt[(size_t)(nb + ty + j * 8) * K + kb + tx] = f2b(t[tx][ty + j * 8]);
}

// ---------------- K1: coordinate pooled means ----------------
__global__ void k_mean(const float* __restrict__ x, float* __restrict__ mh, float* __restrict__ mw) {
    int bc = blockIdx.x;
    const float* p = x + (size_t)bc * 4096;
    int w = threadIdx.x;
    __shared__ float part[128];
    float colsum = 0.f;
    for (int r = 0; r < 64; r++) {
        float v = p[r * 64 + w];
        colsum += v;
        float s = v;
#pragma unroll
        for (int o = 16; o > 0; o >>= 1) s += __shfl_down_sync(0xffffffffu, s, o);
        if ((w & 31) == 0) part[(w >> 5) * 64 + r] = s;
    }
    __syncthreads();
    mh[(size_t)bc * 64 + w] = (part[w] + part[64 + w]) * (1.f / 64.f);
    mw[(size_t)bc * 64 + w] = colsum * (1.f / 64.f);
}

// ---------------- K2: dwconv1d(k=7) + GroupNorm(16) + ReLU ----------------
__global__ void k_sdagn(const float* __restrict__ mh, const float* __restrict__ mw,
                        const float* __restrict__ w7, const float* __restrict__ gnw,
                        const float* __restrict__ gnb, float* __restrict__ gh, float* __restrict__ gw_) {
    int grp = blockIdx.x, b = blockIdx.y;
    const float* mean = (blockIdx.z ? mw : mh) + (size_t)b * Cq * 64;
    float* out = (blockIdx.z ? gw_ : gh) + (size_t)b * Cq * 64;
    __shared__ float buf[1024];
    __shared__ float sh[64];
    int tid = threadIdx.x;
    float ls = 0.f, lq = 0.f;
#pragma unroll
    for (int j = 0; j < 4; j++) {
        int idx = tid + j * 256;
        int c = grp * 16 + (idx >> 6), l = idx & 63;
        const float* m = mean + c * 64;
        float acc = 0.f;
#pragma unroll
        for (int k = 0; k < 7; k++) {
            int ll = l + k - 3;
            if (ll >= 0 && ll < 64) acc += m[ll] * w7[c * 7 + k];
        }
        buf[idx] = acc; ls += acc; lq += acc * acc;
    }
    blockReduce2(ls, lq, sh);
    float mu = ls * (1.f / 1024.f);
    float rstd = rsqrtf(lq * (1.f / 1024.f) - mu * mu + 1e-5f);
#pragma unroll
    for (int j = 0; j < 4; j++) {
        int idx = tid + j * 256;
        int c = grp * 16 + (idx >> 6), l = idx & 63;
        float y = (buf[idx] - mu) * rstd * gnw[c] + gnb[c];
        out[(size_t)c * 64 + l] = fmaxf(y, 0.f);
    }
}

// ---------------- K3: modulate + to tokens + LN1 (res f32, ln bf16) ----------------
__global__ void k_tokens(const float* __restrict__ x, const float* __restrict__ gh,
                         const float* __restrict__ gw_, const float* __restrict__ n1w,
                         const float* __restrict__ n1b, float* __restrict__ res,
                         __nv_bfloat16* __restrict__ ln) {
    int b = blockIdx.y;
    int n0 = blockIdx.x * 32;
    int h = n0 >> 6, w0 = n0 & 63;
    int nx = threadIdx.x, cy = threadIdx.y;
    __shared__ float tile[256][33];
    __shared__ float mu[32], rs[32];
    const float* ghb = gh + (size_t)b * Cq * 64;
    const float* gwb = gw_ + (size_t)b * Cq * 64;
    const float* xb = x + (size_t)b * Cq * Nq;
#pragma unroll 4
    for (int j = 0; j < 32; j++) {
        int c = cy * 32 + j;
        float v = xb[(size_t)c * Nq + h * 64 + w0 + nx] * ghb[c * 64 + h] * gwb[c * 64 + w0 + nx];
        tile[c][nx] = v;
    }
    __syncthreads();
    int tid = cy * 32 + nx, lane = tid & 31, warp = tid >> 5;
    for (int nn = warp; nn < 32; nn += 8) {
        float s = 0.f, q = 0.f;
        for (int c = lane; c < 256; c += 32) { float v = tile[c][nn]; s += v; q += v * v; }
#pragma unroll
        for (int o = 16; o > 0; o >>= 1) {
            s += __shfl_down_sync(0xffffffffu, s, o);
            q += __shfl_down_sync(0xffffffffu, q, o);
        }
        if (lane == 0) {
            float m = s * (1.f / 256.f);
            mu[nn] = m; rs[nn] = rsqrtf(q * (1.f / 256.f) - m * m + 1e-6f);
        }
    }
    __syncthreads();
    float* resp = res + ((size_t)b * Nq + n0) * Cq;
    __nv_bfloat16* lnp = ln + ((size_t)b * Nq + n0) * Cq;
    for (int idx = tid; idx < 32 * 256; idx += 256) {
        int nl = idx >> 8, c = idx & 255;
        float v = tile[c][nl];
        resp[(size_t)nl * 256 + c] = v;
        lnp[(size_t)nl * 256 + c] = f2b((v - mu[nl]) * rs[nl] * n1w[c] + n1b[c]);
    }
}

// ---------------- reduction path (reads bf16 LN tokens) ----------------
__global__ void k_red1(const __nv_bfloat16* __restrict__ ln1, const float* __restrict__ rw,
                       const float* __restrict__ rb, float* __restrict__ r1) {
    int p = blockIdx.x, b = blockIdx.y, c = threadIdx.x;
    int i = p >> 4, j = p & 15;
    float acc = rb[c];
    const __nv_bfloat16* base = ln1 + (size_t)b * Nq * Cq + c;
#pragma unroll
    for (int a = 0; a < 4; a++)
#pragma unroll
        for (int d = 0; d < 4; d++) {
            int n = (4 * i + a) * 64 + 4 * j + d;
            acc += __bfloat162float(base[(size_t)n * 256]) * rw[c * 16 + a * 4 + d];
        }
    r1[((size_t)b * 256 + p) * 256 + c] = acc;
}

__global__ void k_red2(const float* __restrict__ r1, const float* __restrict__ rw,
                       const float* __restrict__ rb, float* __restrict__ r2) {
    int p2 = blockIdx.x, b = blockIdx.y, c = threadIdx.x;
    int i2 = p2 >> 2, j2 = p2 & 3;
    float acc = rb[c];
#pragma unroll
    for (int a = 0; a < 4; a++)
#pragma unroll
        for (int d = 0; d < 4; d++) {
            int p = (4 * i2 + a) * 16 + (4 * j2 + d);
            acc += r1[((size_t)b * 256 + p) * 256 + c] * rw[c * 16 + a * 4 + d];
        }
    r2[((size_t)b * 16 + p2) * 256 + c] = acc;
}

__global__ void k_dw3(const float* __restrict__ r2, const float* __restrict__ dww,
                      const float* __restrict__ dwb, float* __restrict__ dd) {
    int p = blockIdx.x, b = blockIdx.y, c = threadIdx.x;
    int i = p >> 2, j = p & 3;
    float acc = dwb[c];
#pragma unroll
    for (int a = 0; a < 3; a++) {
        int ii = i + a - 1;
        if (ii < 0 || ii >= 4) continue;
#pragma unroll
        for (int d = 0; d < 3; d++) {
            int jj = j + d - 1;
            if (jj < 0 || jj >= 4) continue;
            acc += r2[((size_t)b * 16 + ii * 4 + jj) * 256 + c] * dww[c * 9 + a * 3 + d];
        }
    }
    dd[((size_t)b * 16 + p) * 256 + c] = acc;
}

__global__ void k_na(const float* __restrict__ dd, const float* __restrict__ cw,
                     const float* __restrict__ cb, const float* __restrict__ naw,
                     const float* __restrict__ nab, float* __restrict__ xa) {
    int p = blockIdx.x, b = blockIdx.y, o = threadIdx.x;
    __shared__ float ds[256];
    __shared__ float sh[64];
    const float* dp = dd + ((size_t)b * 16 + p) * 256;
    ds[o] = dp[o]; ds[o + 128] = dp[o + 128];
    __syncthreads();
    float e = cb[o];
    for (int c = 0; c < 256; c++) e += ds[c] * cw[o * 256 + c];
    float s = e, q = e * e;
    blockReduce2(s, q, sh);
    float mu = s * (1.f / 128.f);
    float rstd = rsqrtf(q * (1.f / 128.f) - mu * mu + 1e-5f);
    float y = (e - mu) * rstd * naw[o] + nab[o];
    xa[((size_t)b * 16 + p) * 128 + o] = gelu_f(y);
}

__global__ void k_kv(const float* __restrict__ xa, const float* __restrict__ kw,
                     const float* __restrict__ vw, float* __restrict__ kk, float* __restrict__ vt) {
    int p = blockIdx.x, b = blockIdx.y, t = threadIdx.x;
    __shared__ float xs[128];
    if (t < 128) xs[t] = xa[((size_t)b * 16 + p) * 128 + t];
    __syncthreads();
    if (t < 128) {
        float a = 0.f;
        for (int c = 0; c < 128; c++) a += xs[c] * kw[c * 128 + t];
        kk[((size_t)b * 16 + p) * 128 + t] = a;
    }
    float a2 = 0.f;
    for (int c = 0; c < 128; c++) a2 += xs[c] * vw[c * 256 + t];
    vt[((size_t)b * 16 + p) * 256 + t] = a2;
}

__global__ void k_cpe(const float* __restrict__ vt, const float* __restrict__ cw,
                      const float* __restrict__ cb, float* __restrict__ v2) {
    int p = blockIdx.x, b = blockIdx.y, ch = threadIdx.x;
    int i = p >> 2, j = p & 3;
    float acc = cb[ch];
#pragma unroll
    for (int a = 0; a < 3; a++) {
        int ii = i + a - 1;
        if (ii < 0 || ii >= 4) continue;
#pragma unroll
        for (int d = 0; d < 3; d++) {
            int jj = j + d - 1;
            if (jj < 0 || jj >= 4) continue;
            acc += vt[((size_t)b * 16 + ii * 4 + jj) * 256 + ch] * cw[ch * 9 + a * 3 + d];
        }
    }
    v2[((size_t)b * 16 + p) * 256 + ch] = vt[((size_t)b * 16 + p) * 256 + ch] + acc;
}

// ---------------- fused attention (writes bf16) ----------------
__global__ void k_attn(const float* __restrict__ q, const float* __restrict__ kk,
                       const float* __restrict__ v2, __nv_bfloat16* __restrict__ ao) {
    __shared__ float ks[8 * 260];
    __shared__ float vs[8 * 516];
    int b = blockIdx.y;
    int tid = threadIdx.x;
    for (int idx = tid; idx < 2048; idx += 256) {
        int head = idx >> 8, r = idx & 255, m = r >> 4, i = r & 15;
        ks[head * 260 + m * 16 + i] = kk[((size_t)b * 16 + m) * 128 + head * 16 + i];
    }
    for (int idx = tid; idx < 4096; idx += 256) {
        int head = idx >> 9, r = idx & 511, m = r >> 5, d = r & 31;
        vs[head * 516 + m * 32 + d] = v2[((size_t)b * 16 + m) * 256 + head * 32 + d];
    }
    __syncthreads();
    int nl = tid >> 3, head = tid & 7;
    int n = blockIdx.x * 32 + nl;
    const float* qp = q + ((size_t)b * Nq + n) * 128 + head * 16;
    float qr[16];
#pragma unroll
    for (int i = 0; i < 16; i++) qr[i] = qp[i];
    const float* kh = ks + head * 260;
    float s[16];
    float mx = -1e30f;
#pragma unroll
    for (int m = 0; m < 16; m++) {
        float a = 0.f;
#pragma unroll
        for (int i = 0; i < 16; i++) a += qr[i] * kh[m * 16 + i];
        a *= 0.25f;
        s[m] = a;
        mx = fmaxf(mx, a);
    }
    float sum = 0.f;
#pragma unroll
    for (int m = 0; m < 16; m++) { s[m] = __expf(s[m] - mx); sum += s[m]; }
    float inv = 1.f / sum;
    float o[32];
#pragma unroll
    for (int d = 0; d < 32; d++) o[d] = 0.f;
    const float* vh = vs + head * 516;
#pragma unroll
    for (int m = 0; m < 16; m++) {
        float pm = s[m] * inv;
#pragma unroll
        for (int d = 0; d < 32; d++) o[d] += pm * vh[m * 32 + d];
    }
    __nv_bfloat16* op = ao + ((size_t)b * Nq + n) * 256 + head * 32;
#pragma unroll
    for (int d = 0; d < 32; d++) op[d] = f2b(o[d]);
}

// ---------------- LayerNorm (f32 in, bf16 out) ----------------
__global__ void k_ln(const float* __restrict__ in, int istr, const float* __restrict__ w,
                     const float* __restrict__ b, __nv_bfloat16* __restrict__ out,
                     int ostr, int D, float eps) {
    size_t row = blockIdx.x;
    const float* ip = in + row * (size_t)istr;
    int cnt = D >> 8;
    float v[2];
    float s = 0.f, q = 0.f;
    for (int j = 0; j < cnt; j++) {
        float x = ip[threadIdx.x + j * 256];
        v[j] = x; s += x; q += x * x;
    }
    __shared__ float sh[64];
    blockReduce2(s, q, sh);
    float mu = s / (float)D;
    float rstd = rsqrtf(q / (float)D - mu * mu + eps);
    __nv_bfloat16* op = out + row * (size_t)ostr;
    for (int j = 0; j < cnt; j++) {
        int c = threadIdx.x + j * 256;
        op[c] = f2b((v[j] - mu) * rstd * w[c] + b[c]);
    }
}

// ---------------- depthwise 3x3 gate conv + multiply (bf16 in/out) ----------------
__global__ void k_gconv(const __nv_bfloat16* __restrict__ x2, const float* __restrict__ hbuf,
                        const float* __restrict__ gcw, const float* __restrict__ gcb,
                        __nv_bfloat16* __restrict__ gated) {
    int n = blockIdx.x, b = blockIdx.y;
    int hh = n >> 6, ww = n & 63;
    const __nv_bfloat16* xb = x2 + (size_t)b * Nq * 512;
#pragma unroll
    for (int r = 0; r < 2; r++) {
        int ch = threadIdx.x + r * 256;
        float acc = gcb[ch];
#pragma unroll
        for (int a = 0; a < 3; a++) {
            int hi = hh + a - 1;
            if (hi < 0 || hi >= 64) continue;
#pragma unroll
            for (int d = 0; d < 3; d++) {
                int wi = ww + d - 1;
                if (wi < 0 || wi >= 64) continue;
                acc += __bfloat162float(xb[(size_t)(hi * 64 + wi) * 512 + ch]) * gcw[ch * 9 + a * 3 + d];
            }
        }
        float x1 = hbuf[((size_t)b * Nq + n) * 1024 + ch];
        gated[((size_t)b * Nq + n) * 512 + ch] = f2b(x1 * acc);
    }
}

// ---------------- final transpose ----------------
__global__ void k_tr(const float* __restrict__ tf, float* __restrict__ out) {
    __shared__ float t[32][33];
    int n0 = blockIdx.x * 32, c0 = blockIdx.y * 32, b = blockIdx.z;
    const float* ip = tf + (size_t)b * Nq * Cq;
    float* op = out + (size_t)b * Cq * Nq;
#pragma unroll
    for (int j = 0; j < 4; j++) {
        int i = threadIdx.y + j * 8;
        t[i][threadIdx.x] = ip[(size_t)(n0 + i) * 256 + c0 + threadIdx.x];
    }
    __syncthreads();
#pragma unroll
    for (int j = 0; j < 4; j++) {
        int i = threadIdx.y + j * 8;
        op[(size_t)(c0 + i) * 4096 + n0 + threadIdx.x] = t[threadIdx.x][i];
    }
}

// ---------------- host launch ----------------
extern "C" void kernel_launch(void* const* d_in, const int* in_sizes, int n_in,
                              void* d_out, int out_size) {
    const float* x          = (const float*)d_in[0];
    const float* sda_conv_w = (const float*)d_in[1];
    const float* sda_gn_w   = (const float*)d_in[2];
    const float* sda_gn_b   = (const float*)d_in[3];
    const float* norm1_w    = (const float*)d_in[4];
    const float* norm1_b    = (const float*)d_in[5];
    const float* red_w      = (const float*)d_in[6];
    const float* red_b      = (const float*)d_in[7];
    const float* dw_w       = (const float*)d_in[8];
    const float* dw_b       = (const float*)d_in[9];
    const float* conv_w     = (const float*)d_in[10];
    const float* conv_b     = (const float*)d_in[11];
    const float* na_w       = (const float*)d_in[12];
    const float* na_b       = (const float*)d_in[13];
    const float* q_w        = (const float*)d_in[14];
    const float* k_w        = (const float*)d_in[15];
    const float* v_w        = (const float*)d_in[16];
    const float* cpe_w      = (const float*)d_in[17];
    const float* cpe_b      = (const float*)d_in[18];
    const float* proj_w     = (const float*)d_in[19];
    const float* proj_b     = (const float*)d_in[20];
    const float* norm2_w    = (const float*)d_in[21];
    const float* norm2_b    = (const float*)d_in[22];
    const float* fc1_w      = (const float*)d_in[23];
    const float* fc1_b      = (const float*)d_in[24];
    const float* gnorm_w    = (const float*)d_in[25];
    const float* gnorm_b    = (const float*)d_in[26];
    const float* gconv_w    = (const float*)d_in[27];
    const float* gconv_b    = (const float*)d_in[28];
    const float* fc2_w      = (const float*)d_in[29];
    const float* fc2_b      = (const float*)d_in[30];

    float* S;
    cudaGetSymbolAddress((void**)&S, g_s);
    float* mh   = S + OFF_MH;
    float* mw   = S + OFF_MW;
    float* gh   = S + OFF_GH;
    float* gw   = S + OFF_GW;
    float* res1 = S + OFF_RES1;
    __nv_bfloat16* lnb = (__nv_bfloat16*)(S + OFF_LNB);
    float* qq   = S + OFF_Q;
    float* r1   = S + OFF_R1;
    float* r2   = S + OFF_R2;
    float* dd   = S + OFF_D;
    float* xa   = S + OFF_XA;
    float* kk   = S + OFF_K;
    float* vt   = S + OFF_VT;
    float* v2   = S + OFF_V2;
    __nv_bfloat16* aob  = (__nv_bfloat16*)(S + OFF_AOB);
    float* t2   = S + OFF_T2;
    __nv_bfloat16* ln2b = (__nv_bfloat16*)(S + OFF_LN2B);
    float* hbuf = S + OFF_HH;
    __nv_bfloat16* x2b  = (__nv_bfloat16*)(S + OFF_X2B);
    __nv_bfloat16* gtb  = (__nv_bfloat16*)(S + OFF_GTB);
    float* tf   = S + OFF_TF;
    __nv_bfloat16* wtq  = (__nv_bfloat16*)(S + OFF_WTQ);
    __nv_bfloat16* wtp  = (__nv_bfloat16*)(S + OFF_WTP);
    __nv_bfloat16* wt1  = (__nv_bfloat16*)(S + OFF_WT1);
    __nv_bfloat16* wt2  = (__nv_bfloat16*)(S + OFF_WT2);

    cudaFuncSetAttribute(k_bf_gemm<0>, cudaFuncAttributeMaxDynamicSharedMemorySize, DSMB);
    cudaFuncSetAttribute(k_bf_gemm<3>, cudaFuncAttributeMaxDynamicSharedMemorySize, DSMB);
    cudaFuncSetAttribute(k_bf_gemm<5>, cudaFuncAttributeMaxDynamicSharedMemorySize, DSMB);

    // weight transposes -> bf16 K-major
    k_wt<<<dim3(4, 8), dim3(32, 8)>>>(q_w, wtq, 256, 128);
    k_wt<<<dim3(8, 8), dim3(32, 8)>>>(proj_w, wtp, 256, 256);
    k_wt<<<dim3(32, 8), dim3(32, 8)>>>(fc1_w, wt1, 256, 1024);
    k_wt<<<dim3(8, 16), dim3(32, 8)>>>(fc2_w, wt2, 512, 256);

    // SDAM
    k_mean<<<Bq * Cq, 64>>>(x, mh, mw);
    k_sdagn<<<dim3(16, Bq, 2), 256>>>(mh, mw, sda_conv_w, sda_gn_w, sda_gn_b, gh, gw);
    k_tokens<<<dim3(128, Bq), dim3(32, 8)>>>(x, gh, gw, norm1_w, norm1_b, res1, lnb);

    // reduced path
    k_red1<<<dim3(256, Bq), 256>>>(lnb, red_w, red_b, r1);
    k_red2<<<dim3(16, Bq), 256>>>(r1, red_w, red_b, r2);
    k_dw3<<<dim3(16, Bq), 256>>>(r2, dw_w, dw_b, dd);
    k_na<<<dim3(16, Bq), 128>>>(dd, conv_w, conv_b, na_w, na_b, xa);
    k_kv<<<dim3(16, Bq), 256>>>(xa, k_w, v_w, kk, vt);
    k_cpe<<<dim3(16, Bq), 256>>>(vt, cpe_w, cpe_b, v2);

    // q projection (M=65536, N=128, K=256)
    k_bf_gemm<0><<<dim3(1, Mrows / 128), 256, DSMB>>>(lnb, wtq, nullptr, nullptr, qq, Mrows, 128, 256);

    // attention
    k_attn<<<dim3(128, Bq), 256>>>(qq, kk, v2, aob);

    // proj + bias + residual
    k_bf_gemm<5><<<dim3(2, Mrows / 128), 256, DSMB>>>(aob, wtp, proj_b, res1, t2, Mrows, 256, 256);

    // MLP
    k_ln<<<Mrows, 256>>>(t2, 256, norm2_w, norm2_b, ln2b, 256, 256, 1e-6f);
    k_bf_gemm<3><<<dim3(8, Mrows / 128), 256, DSMB>>>(ln2b, wt1, fc1_b, nullptr, hbuf, Mrows, 1024, 256);
    k_ln<<<Mrows, 256>>>(hbuf + 512, 1024, gnorm_w, gnorm_b, x2b, 512, 512, 1e-5f);
    k_gconv<<<dim3(4096, Bq), 256>>>(x2b, hbuf, gconv_w, gconv_b, gtb);
    k_bf_gemm<5><<<dim3(2, Mrows / 128), 256, DSMB>>>(gtb, wt2, fc2_b, t2, tf, Mrows, 256, 512);

    // output transpose
    k_tr<<<dim3(128, 8, Bq), dim3(32, 8)>>>(tf, (float*)d_out);
}

// round 8
// speedup vs baseline: 2.3610x; 1.0591x over previous
#include <cuda_runtime.h>
#include <cuda_bf16.h>
#include <math.h>
#include <stdint.h>
#include <mma.h>

using namespace nvcuda;

// ---------------- problem constants ----------------
#define Bq 16
#define Cq 256
#define Hq 64
#define Wq 64
#define Nq 4096
#define NHq 8
#define CRq 128
#define HIDq 1024
#define HALFq 512
#define Mrows (Bq*Nq)      // 65536

// ---------------- scratch layout (float units) ----------------
#define OFF_MH    0ull
#define OFF_MW    262144ull
#define OFF_GH    524288ull
#define OFF_GW    786432ull
#define OFF_RES1  1048576ull      // f32  [M,256]
#define OFF_LNB   17825792ull     // bf16 [M,256]
#define OFF_QB    26214400ull     // bf16 [M,128]
#define OFF_R1    30408704ull     // f32  [B,256,256]
#define OFF_R2    31457280ull
#define OFF_D     31522816ull
#define OFF_XA    31588352ull
#define OFF_K     31621120ull
#define OFF_VT    31653888ull
#define OFF_V2    31719424ull
#define OFF_AOB   31784960ull     // bf16 [M,256]
#define OFF_T2    40173568ull     // f32  [M,256]
#define OFF_LN2B  56950784ull     // bf16 [M,256]
#define OFF_X1B   65339392ull     // bf16 [M,512]
#define OFF_X2B   82116608ull     // bf16 [M,512]
#define OFF_X2LN  98893824ull     // bf16 [M,512]
#define OFF_GTB   115671040ull    // bf16 [M,512]
#define OFF_WTQ   132448256ull    // bf16 [128,256]
#define OFF_WTP   132464640ull    // bf16 [256,256]
#define OFF_WT1   132497408ull    // bf16 [1024,256]
#define OFF_WT2   132628480ull    // bf16 [256,512]
#define G_TOTAL   132694016ull

static __device__ float g_s[G_TOTAL];

#define DINL __device__ __forceinline__

DINL float gelu_f(float x) { return 0.5f * x * (1.0f + erff(x * 0.70710678118654752f)); }
DINL __nv_bfloat16 f2b(float x) { return __float2bfloat16_rn(x); }

DINL void blockReduce2(float& s, float& q, float* sh) {
    int lane = threadIdx.x & 31, wid = threadIdx.x >> 5;
#pragma unroll
    for (int o = 16; o > 0; o >>= 1) {
        s += __shfl_down_sync(0xffffffffu, s, o);
        q += __shfl_down_sync(0xffffffffu, q, o);
    }
    if (lane == 0) { sh[wid] = s; sh[32 + wid] = q; }
    __syncthreads();
    if (threadIdx.x == 0) {
        float ss = 0.f, qq = 0.f;
        int nw = blockDim.x >> 5;
        for (int i = 0; i < nw; i++) { ss += sh[i]; qq += sh[32 + i]; }
        sh[0] = ss; sh[32] = qq;
    }
    __syncthreads();
    s = sh[0]; q = sh[32];
}

// ================= wmma bf16 GEMM, 4-stage pipeline =================
// C = A[M,K] @ BT[N,K]^T. OP bits: 1 bias, 2 gelu, 4 residual,
// 8 split-bf16 out (fc1: cols<512 -> Cv, else C2v), 16 transposed f32 out (fc2 -> [B,C,HW]),
// 32 plain bf16 out. CTA 128x128, K-chunk 32, 256 threads (8 warps 2x4, 64x32 each).
#define KC 32
#define LDE 40                       // bf16 elems per smem row (32 data + 8 pad = 80B)
#define STG_E (256*LDE)              // elems per stage (128 A rows + 128 B rows)
#define NSTG 4
#define DSMB (NSTG*STG_E*2)          // 81920 bytes

template <int OP>
__global__ __launch_bounds__(256) void k_bf_gemm(const __nv_bfloat16* __restrict__ A,
        const __nv_bfloat16* __restrict__ BT, const float* __restrict__ bias,
        const float* __restrict__ res, void* __restrict__ Cv, void* __restrict__ C2v,
        int M, int N, int K) {
    extern __shared__ __align__(16) char dsm[];
    __nv_bfloat16* sm = (__nv_bfloat16*)dsm;
    __shared__ float sbias[128];
    int tid = threadIdx.x;
    int m0 = blockIdx.y << 7, n0 = blockIdx.x << 7;
    if ((OP & 1) && tid < 128) sbias[tid] = bias[n0 + tid];

    int w = tid >> 5;
    int wm = w >> 2, wn = w & 3;     // 2x4 warps: 64-row x 32-col tiles

    wmma::fragment<wmma::accumulator, 16, 16, 16, float> acc[4][2];
#pragma unroll
    for (int mi = 0; mi < 4; mi++)
#pragma unroll
        for (int ni = 0; ni < 2; ni++) wmma::fill_fragment(acc[mi][ni], 0.f);

    // loader: seg (16B) 0..3 within 64B k-row; rows r0 + 64*it
    int seg = tid & 3, r0 = tid >> 2;
    const __nv_bfloat16* Ag = A + (size_t)(m0 + r0) * K + seg * 8;
    const __nv_bfloat16* Bg = BT + (size_t)(n0 + r0) * K + seg * 8;
    uint32_t sbase = (uint32_t)__cvta_generic_to_shared(sm);
    int nk = K >> 5;

#define ISSUE_CHUNK(i)                                                               \
    {                                                                                \
        uint32_t ba = sbase + (uint32_t)(((i) & 3) * (STG_E * 2))                    \
                    + (uint32_t)(r0 * 80 + seg * 16);                                \
        const __nv_bfloat16* ga = Ag + (i) * KC;                                     \
        const __nv_bfloat16* gb = Bg + (i) * KC;                                     \
        _Pragma("unroll")                                                            \
        for (int it = 0; it < 2; it++)                                               \
            asm volatile("cp.async.cg.shared.global [%0], [%1], 16;"                 \
                :: "r"(ba + it * (64u * 80u)), "l"(ga + (size_t)it * 64 * K)         \
                : "memory");                                                         \
        _Pragma("unroll")                                                            \
        for (int it = 0; it < 2; it++)                                               \
            asm volatile("cp.async.cg.shared.global [%0], [%1], 16;"                 \
                :: "r"(ba + 10240u + it * (64u * 80u)), "l"(gb + (size_t)it * 64 * K)\
                : "memory");                                                         \
        asm volatile("cp.async.commit_group;");                                      \
    }

    ISSUE_CHUNK(0); ISSUE_CHUNK(1); ISSUE_CHUNK(2);
    for (int i = 0; i < nk; i++) {
        asm volatile("cp.async.wait_group 2;");
        __syncthreads();   // all chunk-i data visible; everyone done with chunk i-1's buffer owner
        if (i + 3 < nk) { ISSUE_CHUNK(i + 3); }
        else { asm volatile("cp.async.commit_group;"); }
        const __nv_bfloat16* As = sm + (i & 3) * STG_E;
        const __nv_bfloat16* Bs = As + 128 * LDE;
#pragma unroll
        for (int kk = 0; kk < KC; kk += 16) {
            wmma::fragment<wmma::matrix_a, 16, 16, 16, __nv_bfloat16, wmma::row_major> af[4];
            wmma::fragment<wmma::matrix_b, 16, 16, 16, __nv_bfloat16, wmma::col_major> bf[2];
#pragma unroll
            for (int mi = 0; mi < 4; mi++)
                wmma::load_matrix_sync(af[mi], As + (wm * 64 + mi * 16) * LDE + kk, LDE);
#pragma unroll
            for (int ni = 0; ni < 2; ni++)
                wmma::load_matrix_sync(bf[ni], Bs + (wn * 32 + ni * 16) * LDE + kk, LDE);
#pragma unroll
            for (int mi = 0; mi < 4; mi++)
#pragma unroll
                for (int ni = 0; ni < 2; ni++)
                    wmma::mma_sync(acc[mi][ni], af[mi], bf[ni], acc[mi][ni]);
        }
    }
    __syncthreads();

    // stage accumulators through smem
    float* Cs = (float*)dsm;
#pragma unroll
    for (int mi = 0; mi < 4; mi++)
#pragma unroll
        for (int ni = 0; ni < 2; ni++)
            wmma::store_matrix_sync(Cs + (wm * 64 + mi * 16) * 132 + wn * 32 + ni * 16,
                                    acc[mi][ni], 132, wmma::mem_row_major);
    __syncthreads();

    int col = tid & 127, rr = tid >> 7;
    if (OP & 8) {
        // fc1 split: gelu'd halves to two bf16 buffers
        __nv_bfloat16* dst = (n0 < 512) ? (__nv_bfloat16*)Cv : (__nv_bfloat16*)C2v;
        int nloc = n0 & 511;
#pragma unroll 4
        for (int r = rr; r < 128; r += 2) {
            float v = Cs[r * 132 + col] + sbias[col];
            dst[(size_t)(m0 + r) * 512 + nloc + col] = f2b(gelu_f(v));
        }
    } else if (OP & 16) {
        // fc2: bias + residual, then transposed write to [B, C, HW] f32
        const float* Rp = res + (size_t)m0 * N + n0 + col;
#pragma unroll 4
        for (int r = rr; r < 128; r += 2) {
            float v = Cs[r * 132 + col] + sbias[col] + Rp[(size_t)r * N];
            Cs[r * 132 + col] = v;
        }
        __syncthreads();
        int b = m0 >> 12, pix0 = m0 & 4095;
        float* outp = (float*)Cv + (size_t)b * Cq * Nq + pix0 + (tid & 127);
        int ch = tid >> 7;
        int m = tid & 127;
#pragma unroll 4
        for (int cc = 0; cc < 64; cc++) {
            int c = cc * 2 + ch;
            outp[(size_t)(n0 + c) * Nq - (tid & 127) + m] = Cs[m * 132 + c];
        }
    } else if (OP & 32) {
        // plain bf16 out (q projection)
        __nv_bfloat16* dst = (__nv_bfloat16*)Cv;
#pragma unroll 4
        for (int r = rr; r < 128; r += 2)
            dst[(size_t)(m0 + r) * N + n0 + col] = f2b(Cs[r * 132 + col]);
    } else {
        // f32 out with optional bias/gelu/residual (proj)
        float* Cp = (float*)Cv + (size_t)m0 * N + n0 + col;
        const float* Rp = res + (size_t)m0 * N + n0 + col;
#pragma unroll 4
        for (int r = rr; r < 128; r += 2) {
            float v = Cs[r * 132 + col];
            if (OP & 1) v += sbias[col];
            if (OP & 2) v = gelu_f(v);
            if (OP & 4) v += Rp[(size_t)r * N];
            Cp[(size_t)r * N] = v;
        }
    }
}

// weight transpose + bf16 convert: w[K,N] -> wt[N,K] bf16
__global__ void k_wt(const float* __restrict__ w, __nv_bfloat16* __restrict__ wt, int K, int N) {
    __shared__ float t[32][33];
    int nb = blockIdx.x * 32, kb = blockIdx.y * 32;
    int tx = threadIdx.x, ty = threadIdx.y;
#pragma unroll
    for (int j = 0; j < 4; j++)
        t[ty + j * 8][tx] = w[(size_t)(kb + ty + j * 8) * N + nb + tx];
    __syncthreads();
#pragma unroll
    for (int j = 0; j < 4; j++)
        wt[(size_t)(nb + ty + j * 8) * K + kb + tx] = f2b(t[tx][ty + j * 8]);
}

// ---------------- K1: coordinate pooled means ----------------
__global__ void k_mean(const float* __restrict__ x, float* __restrict__ mh, float* __restrict__ mw) {
    int bc = blockIdx.x;
    const float* p = x + (size_t)bc * 4096;
    int w = threadIdx.x;
    __shared__ float part[128];
    float colsum = 0.f;
    for (int r = 0; r < 64; r++) {
        float v = p[r * 64 + w];
        colsum += v;
        float s = v;
#pragma unroll
        for (int o = 16; o > 0; o >>= 1) s += __shfl_down_sync(0xffffffffu, s, o);
        if ((w & 31) == 0) part[(w >> 5) * 64 + r] = s;
    }
    __syncthreads();
    mh[(size_t)bc * 64 + w] = (part[w] + part[64 + w]) * (1.f / 64.f);
    mw[(size_t)bc * 64 + w] = colsum * (1.f / 64.f);
}

// ---------------- K2: dwconv1d(k=7) + GroupNorm(16) + ReLU ----------------
__global__ void k_sdagn(const float* __restrict__ mh, const float* __restrict__ mw,
                        const float* __restrict__ w7, const float* __restrict__ gnw,
                        const float* __restrict__ gnb, float* __restrict__ gh, float* __restrict__ gw_) {
    int grp = blockIdx.x, b = blockIdx.y;
    const float* mean = (blockIdx.z ? mw : mh) + (size_t)b * Cq * 64;
    float* out = (blockIdx.z ? gw_ : gh) + (size_t)b * Cq * 64;
    __shared__ float buf[1024];
    __shared__ float sh[64];
    int tid = threadIdx.x;
    float ls = 0.f, lq = 0.f;
#pragma unroll
    for (int j = 0; j < 4; j++) {
        int idx = tid + j * 256;
        int c = grp * 16 + (idx >> 6), l = idx & 63;
        const float* m = mean + c * 64;
        float acc = 0.f;
#pragma unroll
        for (int k = 0; k < 7; k++) {
            int ll = l + k - 3;
            if (ll >= 0 && ll < 64) acc += m[ll] * w7[c * 7 + k];
        }
        buf[idx] = acc; ls += acc; lq += acc * acc;
    }
    blockReduce2(ls, lq, sh);
    float mu = ls * (1.f / 1024.f);
    float rstd = rsqrtf(lq * (1.f / 1024.f) - mu * mu + 1e-5f);
#pragma unroll
    for (int j = 0; j < 4; j++) {
        int idx = tid + j * 256;
        int c = grp * 16 + (idx >> 6), l = idx & 63;
        float y = (buf[idx] - mu) * rstd * gnw[c] + gnb[c];
        out[(size_t)c * 64 + l] = fmaxf(y, 0.f);
    }
}

// ---------------- K3: modulate + to tokens + LN1 ----------------
__global__ void k_tokens(const float* __restrict__ x, const float* __restrict__ gh,
                         const float* __restrict__ gw_, const float* __restrict__ n1w,
                         const float* __restrict__ n1b, float* __restrict__ res,
                         __nv_bfloat16* __restrict__ ln) {
    int b = blockIdx.y;
    int n0 = blockIdx.x * 32;
    int h = n0 >> 6, w0 = n0 & 63;
    int nx = threadIdx.x, cy = threadIdx.y;
    __shared__ float tile[256][33];
    __shared__ float mu[32], rs[32];
    const float* ghb = gh + (size_t)b * Cq * 64;
    const float* gwb = gw_ + (size_t)b * Cq * 64;
    const float* xb = x + (size_t)b * Cq * Nq;
#pragma unroll 4
    for (int j = 0; j < 32; j++) {
        int c = cy * 32 + j;
        float v = xb[(size_t)c * Nq + h * 64 + w0 + nx] * ghb[c * 64 + h] * gwb[c * 64 + w0 + nx];
        tile[c][nx] = v;
    }
    __syncthreads();
    int tid = cy * 32 + nx, lane = tid & 31, warp = tid >> 5;
    for (int nn = warp; nn < 32; nn += 8) {
        float s = 0.f, q = 0.f;
        for (int c = lane; c < 256; c += 32) { float v = tile[c][nn]; s += v; q += v * v; }
#pragma unroll
        for (int o = 16; o > 0; o >>= 1) {
            s += __shfl_down_sync(0xffffffffu, s, o);
            q += __shfl_down_sync(0xffffffffu, q, o);
        }
        if (lane == 0) {
            float m = s * (1.f / 256.f);
            mu[nn] = m; rs[nn] = rsqrtf(q * (1.f / 256.f) - m * m + 1e-6f);
        }
    }
    __syncthreads();
    float* resp = res + ((size_t)b * Nq + n0) * Cq;
    __nv_bfloat16* lnp = ln + ((size_t)b * Nq + n0) * Cq;
    for (int idx = tid; idx < 32 * 256; idx += 256) {
        int nl = idx >> 8, c = idx & 255;
        float v = tile[c][nl];
        resp[(size_t)nl * 256 + c] = v;
        lnp[(size_t)nl * 256 + c] = f2b((v - mu[nl]) * rs[nl] * n1w[c] + n1b[c]);
    }
}

// ---------------- reduction path ----------------
__global__ void k_red1(const __nv_bfloat16* __restrict__ ln1, const float* __restrict__ rw,
                       const float* __restrict__ rb, float* __restrict__ r1) {
    int p = blockIdx.x, b = blockIdx.y, c = threadIdx.x;
    int i = p >> 4, j = p & 15;
    float acc = rb[c];
    const __nv_bfloat16* base = ln1 + (size_t)b * Nq * Cq + c;
#pragma unroll
    for (int a = 0; a < 4; a++)
#pragma unroll
        for (int d = 0; d < 4; d++) {
            int n = (4 * i + a) * 64 + 4 * j + d;
            acc += __bfloat162float(base[(size_t)n * 256]) * rw[c * 16 + a * 4 + d];
        }
    r1[((size_t)b * 256 + p) * 256 + c] = acc;
}

__global__ void k_red2(const float* __restrict__ r1, const float* __restrict__ rw,
                       const float* __restrict__ rb, float* __restrict__ r2) {
    int p2 = blockIdx.x, b = blockIdx.y, c = threadIdx.x;
    int i2 = p2 >> 2, j2 = p2 & 3;
    float acc = rb[c];
#pragma unroll
    for (int a = 0; a < 4; a++)
#pragma unroll
        for (int d = 0; d < 4; d++) {
            int p = (4 * i2 + a) * 16 + (4 * j2 + d);
            acc += r1[((size_t)b * 256 + p) * 256 + c] * rw[c * 16 + a * 4 + d];
        }
    r2[((size_t)b * 16 + p2) * 256 + c] = acc;
}

__global__ void k_dw3(const float* __restrict__ r2, const float* __restrict__ dww,
                      const float* __restrict__ dwb, float* __restrict__ dd) {
    int p = blockIdx.x, b = blockIdx.y, c = threadIdx.x;
    int i = p >> 2, j = p & 3;
    float acc = dwb[c];
#pragma unroll
    for (int a = 0; a < 3; a++) {
        int ii = i + a - 1;
        if (ii < 0 || ii >= 4) continue;
#pragma unroll
        for (int d = 0; d < 3; d++) {
            int jj = j + d - 1;
            if (jj < 0 || jj >= 4) continue;
            acc += r2[((size_t)b * 16 + ii * 4 + jj) * 256 + c] * dww[c * 9 + a * 3 + d];
        }
    }
    dd[((size_t)b * 16 + p) * 256 + c] = acc;
}

__global__ void k_na(const float* __restrict__ dd, const float* __restrict__ cw,
                     const float* __restrict__ cb, const float* __restrict__ naw,
                     const float* __restrict__ nab, float* __restrict__ xa) {
    int p = blockIdx.x, b = blockIdx.y, o = threadIdx.x;
    __shared__ float ds[256];
    __shared__ float sh[64];
    const float* dp = dd + ((size_t)b * 16 + p) * 256;
    ds[o] = dp[o]; ds[o + 128] = dp[o + 128];
    __syncthreads();
    float e = cb[o];
    for (int c = 0; c < 256; c++) e += ds[c] * cw[o * 256 + c];
    float s = e, q = e * e;
    blockReduce2(s, q, sh);
    float mu = s * (1.f / 128.f);
    float rstd = rsqrtf(q * (1.f / 128.f) - mu * mu + 1e-5f);
    float y = (e - mu) * rstd * naw[o] + nab[o];
    xa[((size_t)b * 16 + p) * 128 + o] = gelu_f(y);
}

__global__ void k_kv(const float* __restrict__ xa, const float* __restrict__ kw,
                     const float* __restrict__ vw, float* __restrict__ kk, float* __restrict__ vt) {
    int p = blockIdx.x, b = blockIdx.y, t = threadIdx.x;
    __shared__ float xs[128];
    if (t < 128) xs[t] = xa[((size_t)b * 16 + p) * 128 + t];
    __syncthreads();
    if (t < 128) {
        float a = 0.f;
        for (int c = 0; c < 128; c++) a += xs[c] * kw[c * 128 + t];
        kk[((size_t)b * 16 + p) * 128 + t] = a;
    }
    float a2 = 0.f;
    for (int c = 0; c < 128; c++) a2 += xs[c] * vw[c * 256 + t];
    vt[((size_t)b * 16 + p) * 256 + t] = a2;
}

__global__ void k_cpe(const float* __restrict__ vt, const float* __restrict__ cw,
                      const float* __restrict__ cb, float* __restrict__ v2) {
    int p = blockIdx.x, b = blockIdx.y, ch = threadIdx.x;
    int i = p >> 2, j = p & 3;
    float acc = cb[ch];
#pragma unroll
    for (int a = 0; a < 3; a++) {
        int ii = i + a - 1;
        if (ii < 0 || ii >= 4) continue;
#pragma unroll
        for (int d = 0; d < 3; d++) {
            int jj = j + d - 1;
            if (jj < 0 || jj >= 4) continue;
            acc += vt[((size_t)b * 16 + ii * 4 + jj) * 256 + ch] * cw[ch * 9 + a * 3 + d];
        }
    }
    v2[((size_t)b * 16 + p) * 256 + ch] = vt[((size_t)b * 16 + p) * 256 + ch] + acc;
}

// ---------------- fused attention (bf16 q in, bf16 out) ----------------
__global__ void k_attn(const __nv_bfloat16* __restrict__ q, const float* __restrict__ kk,
                       const float* __restrict__ v2, __nv_bfloat16* __restrict__ ao) {
    __shared__ float ks[8 * 260];
    __shared__ float vs[8 * 516];
    int b = blockIdx.y;
    int tid = threadIdx.x;
    for (int idx = tid; idx < 2048; idx += 256) {
        int head = idx >> 8, r = idx & 255, m = r >> 4, i = r & 15;
        ks[head * 260 + m * 16 + i] = kk[((size_t)b * 16 + m) * 128 + head * 16 + i];
    }
    for (int idx = tid; idx < 4096; idx += 256) {
        int head = idx >> 9, r = idx & 511, m = r >> 5, d = r & 31;
        vs[head * 516 + m * 32 + d] = v2[((size_t)b * 16 + m) * 256 + head * 32 + d];
    }
    __syncthreads();
    int nl = tid >> 3, head = tid & 7;
    int n = blockIdx.x * 32 + nl;
    const __nv_bfloat16* qp = q + ((size_t)b * Nq + n) * 128 + head * 16;
    float qr[16];
#pragma unroll
    for (int i = 0; i < 16; i++) qr[i] = __bfloat162float(qp[i]);
    const float* kh = ks + head * 260;
    float s[16];
    float mx = -1e30f;
#pragma unroll
    for (int m = 0; m < 16; m++) {
        float a = 0.f;
#pragma unroll
        for (int i = 0; i < 16; i++) a += qr[i] * kh[m * 16 + i];
        a *= 0.25f;
        s[m] = a;
        mx = fmaxf(mx, a);
    }
    float sum = 0.f;
#pragma unroll
    for (int m = 0; m < 16; m++) { s[m] = __expf(s[m] - mx); sum += s[m]; }
    float inv = 1.f / sum;
    float o[32];
#pragma unroll
    for (int d = 0; d < 32; d++) o[d] = 0.f;
    const float* vh = vs + head * 516;
#pragma unroll
    for (int m = 0; m < 16; m++) {
        float pm = s[m] * inv;
#pragma unroll
        for (int d = 0; d < 32; d++) o[d] += pm * vh[m * 32 + d];
    }
    __nv_bfloat16* op = ao + ((size_t)b * Nq + n) * 256 + head * 32;
#pragma unroll
    for (int d = 0; d < 32; d++) op[d] = f2b(o[d]);
}

// ---------------- LayerNorm f32 in -> bf16 out, D=256 ----------------
__global__ void k_ln(const float* __restrict__ in, const float* __restrict__ w,
                     const float* __restrict__ b, __nv_bfloat16* __restrict__ out, float eps) {
    size_t row = blockIdx.x;
    const float* ip = in + row * 256;
    float x = ip[threadIdx.x];
    float s = x, q = x * x;
    __shared__ float sh[64];
    blockReduce2(s, q, sh);
    float mu = s * (1.f / 256.f);
    float rstd = rsqrtf(q * (1.f / 256.f) - mu * mu + eps);
    out[row * 256 + threadIdx.x] = f2b((x - mu) * rstd * w[threadIdx.x] + b[threadIdx.x]);
}

// ---------------- LayerNorm bf16 in -> bf16 out, D=512 ----------------
__global__ void k_lnb(const __nv_bfloat16* __restrict__ in, const float* __restrict__ w,
                      const float* __restrict__ b, __nv_bfloat16* __restrict__ out, float eps) {
    size_t row = blockIdx.x;
    const __nv_bfloat16* ip = in + row * 512;
    float v0 = __bfloat162float(ip[threadIdx.x]);
    float v1 = __bfloat162float(ip[threadIdx.x + 256]);
    float s = v0 + v1, q = v0 * v0 + v1 * v1;
    __shared__ float sh[64];
    blockReduce2(s, q, sh);
    float mu = s * (1.f / 512.f);
    float rstd = rsqrtf(q * (1.f / 512.f) - mu * mu + eps);
    __nv_bfloat16* op = out + row * 512;
    op[threadIdx.x] = f2b((v0 - mu) * rstd * w[threadIdx.x] + b[threadIdx.x]);
    op[threadIdx.x + 256] = f2b((v1 - mu) * rstd * w[threadIdx.x + 256] + b[threadIdx.x + 256]);
}

// ---------------- depthwise 3x3 gate conv + multiply (bf16) ----------------
__global__ void k_gconv(const __nv_bfloat16* __restrict__ x2, const __nv_bfloat16* __restrict__ x1,
                        const float* __restrict__ gcw, const float* __restrict__ gcb,
                        __nv_bfloat16* __restrict__ gated) {
    int n = blockIdx.x, b = blockIdx.y;
    int hh = n >> 6, ww = n & 63;
    const __nv_bfloat16* xb = x2 + (size_t)b * Nq * 512;
#pragma unroll
    for (int r = 0; r < 2; r++) {
        int ch = threadIdx.x + r * 256;
        float acc = gcb[ch];
#pragma unroll
        for (int a = 0; a < 3; a++) {
            int hi = hh + a - 1;
            if (hi < 0 || hi >= 64) continue;
#pragma unroll
            for (int d = 0; d < 3; d++) {
                int wi = ww + d - 1;
                if (wi < 0 || wi >= 64) continue;
                acc += __bfloat162float(xb[(size_t)(hi * 64 + wi) * 512 + ch]) * gcw[ch * 9 + a * 3 + d];
            }
        }
        float g1 = __bfloat162float(x1[((size_t)b * Nq + n) * 512 + ch]);
        gated[((size_t)b * Nq + n) * 512 + ch] = f2b(g1 * acc);
    }
}

// ---------------- host launch ----------------
extern "C" void kernel_launch(void* const* d_in, const int* in_sizes, int n_in,
                              void* d_out, int out_size) {
    const float* x          = (const float*)d_in[0];
    const float* sda_conv_w = (const float*)d_in[1];
    const float* sda_gn_w   = (const float*)d_in[2];
    const float* sda_gn_b   = (const float*)d_in[3];
    const float* norm1_w    = (const float*)d_in[4];
    const float* norm1_b    = (const float*)d_in[5];
    const float* red_w      = (const float*)d_in[6];
    const float* red_b      = (const float*)d_in[7];
    const float* dw_w       = (const float*)d_in[8];
    const float* dw_b       = (const float*)d_in[9];
    const float* conv_w     = (const float*)d_in[10];
    const float* conv_b     = (const float*)d_in[11];
    const float* na_w       = (const float*)d_in[12];
    const float* na_b       = (const float*)d_in[13];
    const float* q_w        = (const float*)d_in[14];
    const float* k_w        = (const float*)d_in[15];
    const float* v_w        = (const float*)d_in[16];
    const float* cpe_w      = (const float*)d_in[17];
    const float* cpe_b      = (const float*)d_in[18];
    const float* proj_w     = (const float*)d_in[19];
    const float* proj_b     = (const float*)d_in[20];
    const float* norm2_w    = (const float*)d_in[21];
    const float* norm2_b    = (const float*)d_in[22];
    const float* fc1_w      = (const float*)d_in[23];
    const float* fc1_b      = (const float*)d_in[24];
    const float* gnorm_w    = (const float*)d_in[25];
    const float* gnorm_b    = (const float*)d_in[26];
    const float* gconv_w    = (const float*)d_in[27];
    const float* gconv_b    = (const float*)d_in[28];
    const float* fc2_w      = (const float*)d_in[29];
    const float* fc2_b      = (const float*)d_in[30];

    float* S;
    cudaGetSymbolAddress((void**)&S, g_s);
    float* mh   = S + OFF_MH;
    float* mw   = S + OFF_MW;
    float* gh   = S + OFF_GH;
    float* gw   = S + OFF_GW;
    float* res1 = S + OFF_RES1;
    __nv_bfloat16* lnb  = (__nv_bfloat16*)(S + OFF_LNB);
    __nv_bfloat16* qb   = (__nv_bfloat16*)(S + OFF_QB);
    float* r1   = S + OFF_R1;
    float* r2   = S + OFF_R2;
    float* dd   = S + OFF_D;
    float* xa   = S + OFF_XA;
    float* kk   = S + OFF_K;
    float* vt   = S + OFF_VT;
    float* v2   = S + OFF_V2;
    __nv_bfloat16* aob  = (__nv_bfloat16*)(S + OFF_AOB);
    float* t2   = S + OFF_T2;
    __nv_bfloat16* ln2b = (__nv_bfloat16*)(S + OFF_LN2B);
    __nv_bfloat16* x1b  = (__nv_bfloat16*)(S + OFF_X1B);
    __nv_bfloat16* x2b  = (__nv_bfloat16*)(S + OFF_X2B);
    __nv_bfloat16* x2ln = (__nv_bfloat16*)(S + OFF_X2LN);
    __nv_bfloat16* gtb  = (__nv_bfloat16*)(S + OFF_GTB);
    __nv_bfloat16* wtq  = (__nv_bfloat16*)(S + OFF_WTQ);
    __nv_bfloat16* wtp  = (__nv_bfloat16*)(S + OFF_WTP);
    __nv_bfloat16* wt1  = (__nv_bfloat16*)(S + OFF_WT1);
    __nv_bfloat16* wt2  = (__nv_bfloat16*)(S + OFF_WT2);

    cudaFuncSetAttribute(k_bf_gemm<32>, cudaFuncAttributeMaxDynamicSharedMemorySize, DSMB);
    cudaFuncSetAttribute(k_bf_gemm<5>,  cudaFuncAttributeMaxDynamicSharedMemorySize, DSMB);
    cudaFuncSetAttribute(k_bf_gemm<11>, cudaFuncAttributeMaxDynamicSharedMemorySize, DSMB);
    cudaFuncSetAttribute(k_bf_gemm<21>, cudaFuncAttributeMaxDynamicSharedMemorySize, DSMB);

    // weight transposes -> bf16 K-major
    k_wt<<<dim3(4, 8), dim3(32, 8)>>>(q_w, wtq, 256, 128);
    k_wt<<<dim3(8, 8), dim3(32, 8)>>>(proj_w, wtp, 256, 256);
    k_wt<<<dim3(32, 8), dim3(32, 8)>>>(fc1_w, wt1, 256, 1024);
    k_wt<<<dim3(8, 16), dim3(32, 8)>>>(fc2_w, wt2, 512, 256);

    // SDAM
    k_mean<<<Bq * Cq, 64>>>(x, mh, mw);
    k_sdagn<<<dim3(16, Bq, 2), 256>>>(mh, mw, sda_conv_w, sda_gn_w, sda_gn_b, gh, gw);
    k_tokens<<<dim3(128, Bq), dim3(32, 8)>>>(x, gh, gw, norm1_w, norm1_b, res1, lnb);

    // reduced path
    k_red1<<<dim3(256, Bq), 256>>>(lnb, red_w, red_b, r1);
    k_red2<<<dim3(16, Bq), 256>>>(r1, red_w, red_b, r2);
    k_dw3<<<dim3(16, Bq), 256>>>(r2, dw_w, dw_b, dd);
    k_na<<<dim3(16, Bq), 128>>>(dd, conv_w, conv_b, na_w, na_b, xa);
    k_kv<<<dim3(16, Bq), 256>>>(xa, k_w, v_w, kk, vt);
    k_cpe<<<dim3(16, Bq), 256>>>(vt, cpe_w, cpe_b, v2);

    // q projection -> bf16 (M, 128, K=256)
    k_bf_gemm<32><<<dim3(1, Mrows / 128), 256, DSMB>>>(lnb, wtq, nullptr, nullptr, qb, nullptr, Mrows, 128, 256);

    // attention
    k_attn<<<dim3(128, Bq), 256>>>(qb, kk, v2, aob);

    // proj + bias + residual -> f32 t2
    k_bf_gemm<5><<<dim3(2, Mrows / 128), 256, DSMB>>>(aob, wtp, proj_b, res1, t2, nullptr, Mrows, 256, 256);

    // MLP
    k_ln<<<Mrows, 256>>>(t2, norm2_w, norm2_b, ln2b, 1e-6f);
    k_bf_gemm<11><<<dim3(8, Mrows / 128), 256, DSMB>>>(ln2b, wt1, fc1_b, nullptr, x1b, x2b, Mrows, 1024, 256);
    k_lnb<<<Mrows, 256>>>(x2b, gnorm_w, gnorm_b, x2ln, 1e-5f);
    k_gconv<<<dim3(4096, Bq), 256>>>(x2ln, x1b, gconv_w, gconv_b, gtb);
    // fc2 + bias + residual, fused transpose -> d_out [B,C,H,W]
    k_bf_gemm<21><<<dim3(2, Mrows / 128), 256, DSMB>>>(gtb, wt2, fc2_b, t2, d_out, nullptr, Mrows, 256, 512);
}